// round 7
// baseline (speedup 1.0000x reference)
#include <cuda_runtime.h>
#include <cuda_bf16.h>
#include <cstdint>

#define HH   16
#define DH   64
#define DD   1024
#define SMAX 4096

// Scratch (allocation-free rule: __device__ globals). Head-major [H][S][64].
__device__ float g_q[HH * SMAX * DH];
__device__ float g_k[HH * SMAX * DH];
__device__ float g_v[HH * SMAX * DH];
__device__ float g_ctx[HH * SMAX * DH];

// ---------------------------------------------------------------------------
// GEMM (NT): C[M,N] = A[M,K] * B[N,K]^T + bias[N]
// A_HM: A is head-major [k>>6][m][k&63]; C_HM: C written head-major.
// 128x128 tile, BK=8, 256 threads, 8x8 per thread.
// ---------------------------------------------------------------------------
template<int A_HM, int C_HM>
__global__ __launch_bounds__(256) void gemm_nt_kernel(
    const float* __restrict__ A, const float* __restrict__ B,
    const float* __restrict__ bias, float* __restrict__ C,
    int M, int N, int Kd, int S)
{
    __shared__ float As[8][128];
    __shared__ float Bs[8][128];

    const int t    = threadIdx.x;
    const int m0   = blockIdx.y << 7;
    const int n0   = blockIdx.x << 7;
    const int tx   = t & 15;
    const int ty   = t >> 4;
    const int lrow = t >> 1;
    const int lcol = (t & 1) << 2;

    float acc[8][8];
    #pragma unroll
    for (int i = 0; i < 8; i++)
        #pragma unroll
        for (int j = 0; j < 8; j++) acc[i][j] = 0.0f;

    const float* Bp = B + (size_t)(n0 + lrow) * Kd + lcol;

    for (int k0 = 0; k0 < Kd; k0 += 8) {
        float4 av, bv;
        if (A_HM) {
            int kk = k0 + lcol;
            av = *(const float4*)(A + ((size_t)(kk >> 6) * S + (m0 + lrow)) * DH + (kk & 63));
        } else {
            av = *(const float4*)(A + (size_t)(m0 + lrow) * Kd + k0 + lcol);
        }
        bv = *(const float4*)(Bp + k0);

        __syncthreads();   // previous iteration's reads done
        As[lcol + 0][lrow] = av.x; As[lcol + 1][lrow] = av.y;
        As[lcol + 2][lrow] = av.z; As[lcol + 3][lrow] = av.w;
        Bs[lcol + 0][lrow] = bv.x; Bs[lcol + 1][lrow] = bv.y;
        Bs[lcol + 2][lrow] = bv.z; Bs[lcol + 3][lrow] = bv.w;
        __syncthreads();

        #pragma unroll
        for (int kk = 0; kk < 8; kk++) {
            float a[8], b[8];
            float4 a0 = *(const float4*)(&As[kk][(ty << 3) + 0]);
            float4 a1 = *(const float4*)(&As[kk][(ty << 3) + 4]);
            float4 b0 = *(const float4*)(&Bs[kk][(tx << 3) + 0]);
            float4 b1 = *(const float4*)(&Bs[kk][(tx << 3) + 4]);
            a[0]=a0.x; a[1]=a0.y; a[2]=a0.z; a[3]=a0.w;
            a[4]=a1.x; a[5]=a1.y; a[6]=a1.z; a[7]=a1.w;
            b[0]=b0.x; b[1]=b0.y; b[2]=b0.z; b[3]=b0.w;
            b[4]=b1.x; b[5]=b1.y; b[6]=b1.z; b[7]=b1.w;
            #pragma unroll
            for (int i = 0; i < 8; i++)
                #pragma unroll
                for (int j = 0; j < 8; j++)
                    acc[i][j] += a[i] * b[j];
        }
    }

    #pragma unroll
    for (int i = 0; i < 8; i++) {
        int row = m0 + (ty << 3) + i;
        #pragma unroll
        for (int j = 0; j < 8; j += 4) {
            int col = n0 + (tx << 3) + j;
            float4 bb = *(const float4*)(bias + col);
            float4 o  = make_float4(acc[i][j + 0] + bb.x, acc[i][j + 1] + bb.y,
                                    acc[i][j + 2] + bb.z, acc[i][j + 3] + bb.w);
            if (C_HM)
                *(float4*)(C + ((size_t)(col >> 6) * S + row) * DH + (col & 63)) = o;
            else
                *(float4*)(C + (size_t)row * N + col) = o;
        }
    }
}

// ---------------------------------------------------------------------------
// Causal flash attention. One block = (head, 64-row q tile). 256 threads.
// Q,K stored transposed in smem ([d][r], stride 68) -> conflict-free LDS.128
// in both inner products. P overwrites the K buffer. Online softmax state is
// replicated across each 16-lane half-warp via shfl_xor.
// ---------------------------------------------------------------------------
#define LDT 68
#define ATTN_SMEM (3 * 64 * LDT * 4)

__global__ __launch_bounds__(256) void attn_kernel(
    const float* __restrict__ Q, const float* __restrict__ K,
    const float* __restrict__ V, float* __restrict__ O, int S)
{
    extern __shared__ float sm[];
    float* Qt = sm;                // [64][LDT]  Qt[d][r]
    float* Kt = sm + 64 * LDT;     // [64][LDT]  Kt[d][c]; reused as Pt[c][r]
    float* Vs = sm + 2 * 64 * LDT; // [64][LDT]  Vs[k][c]

    const int h  = blockIdx.y;
    const int i0 = blockIdx.x << 6;
    const float* Qh = Q + (size_t)h * S * DH;
    const float* Kh = K + (size_t)h * S * DH;
    const float* Vh = V + (size_t)h * S * DH;

    const int t  = threadIdx.x;
    const int tx = t & 15;
    const int ty = t >> 4;

    // Q tile, transposed store (conflict-free: per warp d fixed, r = lane)
    #pragma unroll
    for (int u = 0; u < 4; u++) {
        int idx = t + u * 256;
        int r  = idx & 63;
        int d4 = (idx >> 6) << 2;
        float4 qv = *(const float4*)(Qh + (size_t)(i0 + r) * DH + d4);
        Qt[(d4 + 0) * LDT + r] = qv.x;
        Qt[(d4 + 1) * LDT + r] = qv.y;
        Qt[(d4 + 2) * LDT + r] = qv.z;
        Qt[(d4 + 3) * LDT + r] = qv.w;
    }
    __syncthreads();

    float acc[4][4];
    float m_i[4], l_i[4];
    #pragma unroll
    for (int i = 0; i < 4; i++) {
        m_i[i] = -1e30f; l_i[i] = 0.0f;
        #pragma unroll
        for (int j = 0; j < 4; j++) acc[i][j] = 0.0f;
    }

    const int ntiles = blockIdx.x + 1;   // causal: only tiles j0 <= i0
    for (int jt = 0; jt < ntiles; jt++) {
        const int j0 = jt << 6;

        // Prefetch K (transpose mapping) + V (row mapping) into registers
        float4 kreg[4], vreg[4];
        #pragma unroll
        for (int u = 0; u < 4; u++) {
            int idx = t + u * 256;
            int rk = idx & 63;
            int d4 = (idx >> 6) << 2;
            kreg[u] = *(const float4*)(Kh + (size_t)(j0 + rk) * DH + d4);
            int rv = idx >> 4;
            int c4 = (idx & 15) << 2;
            vreg[u] = *(const float4*)(Vh + (size_t)(j0 + rv) * DH + c4);
        }
        __syncthreads();   // previous tile's P/V reads complete
        #pragma unroll
        for (int u = 0; u < 4; u++) {
            int idx = t + u * 256;
            int rk = idx & 63;
            int d4 = (idx >> 6) << 2;
            Kt[(d4 + 0) * LDT + rk] = kreg[u].x;
            Kt[(d4 + 1) * LDT + rk] = kreg[u].y;
            Kt[(d4 + 2) * LDT + rk] = kreg[u].z;
            Kt[(d4 + 3) * LDT + rk] = kreg[u].w;
            int rv = idx >> 4;
            int c4 = (idx & 15) << 2;
            *(float4*)(Vs + rv * LDT + c4) = vreg[u];
        }
        __syncthreads();

        // S = Q K^T  (4x4 per thread)
        float s[4][4];
        #pragma unroll
        for (int i = 0; i < 4; i++)
            #pragma unroll
            for (int j = 0; j < 4; j++) s[i][j] = 0.0f;

        #pragma unroll 8
        for (int d = 0; d < 64; d++) {
            float4 a4 = *(const float4*)(Qt + d * LDT + (ty << 2));
            float4 b4 = *(const float4*)(Kt + d * LDT + (tx << 2));
            float a[4] = {a4.x, a4.y, a4.z, a4.w};
            float b[4] = {b4.x, b4.y, b4.z, b4.w};
            #pragma unroll
            for (int i = 0; i < 4; i++)
                #pragma unroll
                for (int j = 0; j < 4; j++)
                    s[i][j] += a[i] * b[j];
        }

        const float scale = 0.125f;   // 1/sqrt(64)
        if (jt == blockIdx.x) {       // diagonal tile: causal mask
            #pragma unroll
            for (int i = 0; i < 4; i++) {
                int qr = (ty << 2) + i;
                #pragma unroll
                for (int j = 0; j < 4; j++) {
                    int kc = (tx << 2) + j;
                    s[i][j] = (kc <= qr) ? s[i][j] * scale : -1e30f;
                }
            }
        } else {
            #pragma unroll
            for (int i = 0; i < 4; i++)
                #pragma unroll
                for (int j = 0; j < 4; j++) s[i][j] *= scale;
        }

        // Row max across half-warp
        float mc[4];
        #pragma unroll
        for (int i = 0; i < 4; i++)
            mc[i] = fmaxf(fmaxf(s[i][0], s[i][1]), fmaxf(s[i][2], s[i][3]));
        #pragma unroll
        for (int off = 8; off; off >>= 1)
            #pragma unroll
            for (int i = 0; i < 4; i++)
                mc[i] = fmaxf(mc[i], __shfl_xor_sync(0xffffffffu, mc[i], off));

        float alpha[4];
        #pragma unroll
        for (int i = 0; i < 4; i++) {
            float mn = fmaxf(m_i[i], mc[i]);
            alpha[i] = __expf(m_i[i] - mn);
            m_i[i]   = mn;
        }

        float lc[4];
        #pragma unroll
        for (int i = 0; i < 4; i++) {
            #pragma unroll
            for (int j = 0; j < 4; j++) s[i][j] = __expf(s[i][j] - m_i[i]);
            lc[i] = (s[i][0] + s[i][1]) + (s[i][2] + s[i][3]);
        }
        #pragma unroll
        for (int off = 8; off; off >>= 1)
            #pragma unroll
            for (int i = 0; i < 4; i++)
                lc[i] += __shfl_xor_sync(0xffffffffu, lc[i], off);
        #pragma unroll
        for (int i = 0; i < 4; i++) {
            l_i[i] = l_i[i] * alpha[i] + lc[i];
            #pragma unroll
            for (int j = 0; j < 4; j++) acc[i][j] *= alpha[i];
        }

        __syncthreads();   // all K reads done -> safe to overwrite with P
        #pragma unroll
        for (int j = 0; j < 4; j++)
            *(float4*)(Kt + ((tx << 2) + j) * LDT + (ty << 2)) =
                make_float4(s[0][j], s[1][j], s[2][j], s[3][j]);
        __syncthreads();

        // O += P V
        #pragma unroll 8
        for (int k = 0; k < 64; k++) {
            float4 a4 = *(const float4*)(Kt + k * LDT + (ty << 2));
            float4 b4 = *(const float4*)(Vs + k * LDT + (tx << 2));
            float a[4] = {a4.x, a4.y, a4.z, a4.w};
            float b[4] = {b4.x, b4.y, b4.z, b4.w};
            #pragma unroll
            for (int i = 0; i < 4; i++)
                #pragma unroll
                for (int j = 0; j < 4; j++)
                    acc[i][j] += a[i] * b[j];
        }
    }

    #pragma unroll
    for (int i = 0; i < 4; i++) {
        float inv = 1.0f / l_i[i];
        int r = i0 + (ty << 2) + i;
        float4 o = make_float4(acc[i][0] * inv, acc[i][1] * inv,
                               acc[i][2] * inv, acc[i][3] * inv);
        *(float4*)(O + ((size_t)h * S + r) * DH + (tx << 2)) = o;
    }
}

// ---------------------------------------------------------------------------
extern "C" void kernel_launch(void* const* d_in, const int* in_sizes, int n_in,
                              void* d_out, int out_size)
{
    const float* Xq = (const float*)d_in[0];
    const float* Xk = (const float*)d_in[1];
    const float* Xv = (const float*)d_in[2];
    const float* Wq = (const float*)d_in[3];
    const float* bq = (const float*)d_in[4];
    const float* Wk = (const float*)d_in[5];
    const float* bk = (const float*)d_in[6];
    const float* Wv = (const float*)d_in[7];
    const float* bv = (const float*)d_in[8];
    const float* Wo = (const float*)d_in[9];
    const float* bo = (const float*)d_in[10];
    float* out = (float*)d_out;

    const int S = in_sizes[0] / DD;   // 4096

    float *q, *k, *v, *ctx;
    cudaGetSymbolAddress((void**)&q,   g_q);
    cudaGetSymbolAddress((void**)&k,   g_k);
    cudaGetSymbolAddress((void**)&v,   g_v);
    cudaGetSymbolAddress((void**)&ctx, g_ctx);

    dim3 gproj(DD / 128, S / 128);   // (8, 32)

    gemm_nt_kernel<0, 1><<<gproj, 256>>>(Xq, Wq, bq, q, S, DD, DD, S);
    gemm_nt_kernel<0, 1><<<gproj, 256>>>(Xk, Wk, bk, k, S, DD, DD, S);
    gemm_nt_kernel<0, 1><<<gproj, 256>>>(Xv, Wv, bv, v, S, DD, DD, S);

    cudaFuncSetAttribute(attn_kernel,
                         cudaFuncAttributeMaxDynamicSharedMemorySize, ATTN_SMEM);
    attn_kernel<<<dim3(S / 64, HH), 256, ATTN_SMEM>>>(q, k, v, ctx, S);

    gemm_nt_kernel<1, 0><<<gproj, 256>>>(ctx, Wo, bo, out, S, DD, DD, S);
}

// round 9
// speedup vs baseline: 1.3291x; 1.3291x over previous
#include <cuda_runtime.h>
#include <cuda_bf16.h>
#include <cstdint>

#define HH   16
#define DH   64
#define DD   1024
#define SMAX 4096

// Scratch (allocation-free rule: __device__ globals). Head-major [H][S][64].
__device__ float g_q[HH * SMAX * DH];
__device__ float g_k[HH * SMAX * DH];
__device__ float g_v[HH * SMAX * DH];
__device__ float g_ctx[HH * SMAX * DH];

// ===========================================================================
// Warp-level tensor core primitives (baseline PTX, works on compute_103)
// ===========================================================================
__device__ __forceinline__ uint32_t smem_u32(const void* p) {
    uint32_t a;
    asm("{ .reg .u64 t; cvta.to.shared.u64 t, %1; cvt.u32.u64 %0, t; }"
        : "=r"(a) : "l"(p));
    return a;
}

#define LDSM_X4(r0, r1, r2, r3, addr)                                        \
    asm volatile("ldmatrix.sync.aligned.m8n8.x4.shared.b16 {%0,%1,%2,%3}, [%4];" \
                 : "=r"(r0), "=r"(r1), "=r"(r2), "=r"(r3) : "r"(addr))

#define MMA16816(d, a, b0, b1)                                               \
    asm volatile("mma.sync.aligned.m16n8k16.row.col.f32.bf16.bf16.f32 "     \
                 "{%0,%1,%2,%3}, {%4,%5,%6,%7}, {%8,%9}, {%0,%1,%2,%3};"    \
                 : "+f"((d)[0]), "+f"((d)[1]), "+f"((d)[2]), "+f"((d)[3])    \
                 : "r"((a)[0]), "r"((a)[1]), "r"((a)[2]), "r"((a)[3]),       \
                   "r"(b0), "r"(b1))

// Split float4 into bf16 hi + bf16 lo residual, packed as uint2 each.
__device__ __forceinline__ void split_bf16x3(float4 v, uint2& hv, uint2& lv) {
    __nv_bfloat162 h0 = __floats2bfloat162_rn(v.x, v.y);
    __nv_bfloat162 h1 = __floats2bfloat162_rn(v.z, v.w);
    float rx = v.x - __bfloat162float(h0.x);
    float ry = v.y - __bfloat162float(h0.y);
    float rz = v.z - __bfloat162float(h1.x);
    float rw = v.w - __bfloat162float(h1.y);
    __nv_bfloat162 l0 = __floats2bfloat162_rn(rx, ry);
    __nv_bfloat162 l1 = __floats2bfloat162_rn(rz, rw);
    hv = make_uint2(*reinterpret_cast<uint32_t*>(&h0),
                    *reinterpret_cast<uint32_t*>(&h1));
    lv = make_uint2(*reinterpret_cast<uint32_t*>(&l0),
                    *reinterpret_cast<uint32_t*>(&l1));
}

// ===========================================================================
// Tensor-core bf16x3 GEMM (NT): C[M,N] = A[M,K] * B[N,K]^T + bias[N]
// 128x128 CTA tile, BK=32, 8 warps (2M x 4N), warp tile 64x32.
// Smem rows stride 40 bf16 (80B) -> conflict-free ldmatrix, no swizzle.
// A_HM: A head-major [k>>6][m][k&63]; C_HM: C written head-major.
// ===========================================================================
#define RS    40                     // smem row stride in bf16 elems (80 B)
#define TOFF  (128 * RS)             // one 128x32 bf16 tile in elems

template<int A_HM, int C_HM>
__global__ __launch_bounds__(256) void gemm_mma(
    const float* __restrict__ A, const float* __restrict__ B,
    const float* __restrict__ bias, float* __restrict__ C,
    int N, int Kd, int S)
{
    __shared__ __nv_bfloat16 sh[4 * TOFF];   // Ah, Al, Bh, Bl = 40960 B
    const uint32_t sb = smem_u32(sh);
    const uint32_t AH = sb, AL = sb + TOFF * 2,
                   BH = sb + 2 * TOFF * 2, BL = sb + 3 * TOFF * 2;

    const int t    = threadIdx.x;
    const int lane = t & 31, wid = t >> 5;
    const int wm   = wid >> 2;        // 0..1  (64 rows each)
    const int wn   = wid & 3;         // 0..3  (32 cols each)
    const int m0   = blockIdx.y << 7, n0 = blockIdx.x << 7;

    // per-thread load mapping: 4 float4 for A, 4 for B per 128x32 chunk
    const int lrow = t >> 3;          // 0..31 (+32 per u)
    const int lc4  = (t & 7) << 2;    // 0,4,...,28

    // ldmatrix source addresses (byte): A frag rows, B frag rows
    const int a_r  = wm * 64 + (lane & 15);      // + mf*16
    const int a_c  = (lane >> 4) << 3;           // + ks*16
    const int b_g  = lane >> 3;                  // 0..3
    const int b_r  = wn * 32 + ((b_g >> 1) << 3) + (lane & 7);  // + ng*16
    const int b_c  = (b_g & 1) << 3;             // + ks*16

    float acc[4][4][4];
    #pragma unroll
    for (int i = 0; i < 4; i++)
        #pragma unroll
        for (int j = 0; j < 4; j++)
            #pragma unroll
            for (int r = 0; r < 4; r++) acc[i][j][r] = 0.0f;

    const int nch = Kd >> 5;          // 32 chunks of BK=32

    float4 av[4], bv[4];
    // preload chunk 0
    #pragma unroll
    for (int u = 0; u < 4; u++) {
        int row = lrow + (u << 5);
        if (A_HM)
            av[u] = *(const float4*)(A + (size_t)(m0 + row) * DH + lc4);
        else
            av[u] = *(const float4*)(A + (size_t)(m0 + row) * Kd + lc4);
        bv[u] = *(const float4*)(B + (size_t)(n0 + row) * Kd + lc4);
    }

    for (int i = 0; i < nch; i++) {
        __syncthreads();   // previous chunk's ldmatrix reads complete
        // convert + store chunk i
        #pragma unroll
        for (int u = 0; u < 4; u++) {
            int row = lrow + (u << 5);
            uint32_t eo = row * RS + lc4;
            uint2 hv, lv;
            split_bf16x3(av[u], hv, lv);
            *(uint2*)(sh + eo)            = hv;
            *(uint2*)(sh + TOFF + eo)     = lv;
            split_bf16x3(bv[u], hv, lv);
            *(uint2*)(sh + 2 * TOFF + eo) = hv;
            *(uint2*)(sh + 3 * TOFF + eo) = lv;
        }
        __syncthreads();

        // issue global loads for chunk i+1 (overlap with MMA below)
        if (i + 1 < nch) {
            const int k0 = (i + 1) << 5;
            #pragma unroll
            for (int u = 0; u < 4; u++) {
                int row = lrow + (u << 5);
                if (A_HM)
                    av[u] = *(const float4*)(A + ((size_t)(k0 >> 6) * S + m0 + row) * DH
                                               + (k0 & 63) + lc4);
                else
                    av[u] = *(const float4*)(A + (size_t)(m0 + row) * Kd + k0 + lc4);
                bv[u] = *(const float4*)(B + (size_t)(n0 + row) * Kd + k0 + lc4);
            }
        }

        // MMA on chunk i: 2 k16-steps x 3 bf16x3 passes
        #pragma unroll
        for (int ks = 0; ks < 2; ks++) {
            const uint32_t acol = (a_c + (ks << 4)) << 1;   // bytes
            const uint32_t bcol = (b_c + (ks << 4)) << 1;

            uint32_t aH[4][4], aL[4][4], bh[2][4], bl[2][4];
            #pragma unroll
            for (int mf = 0; mf < 4; mf++) {
                uint32_t ra = (uint32_t)(a_r + mf * 16) * (RS * 2);
                LDSM_X4(aH[mf][0], aH[mf][1], aH[mf][2], aH[mf][3], AH + ra + acol);
            }
            #pragma unroll
            for (int ng = 0; ng < 2; ng++) {
                uint32_t rb = (uint32_t)(b_r + ng * 16) * (RS * 2);
                LDSM_X4(bh[ng][0], bh[ng][1], bh[ng][2], bh[ng][3], BH + rb + bcol);
            }
            // pass 1: Ahi * Bhi
            #pragma unroll
            for (int mf = 0; mf < 4; mf++)
                #pragma unroll
                for (int nf = 0; nf < 4; nf++) {
                    const uint32_t* b = bh[nf >> 1] + ((nf & 1) << 1);
                    MMA16816(acc[mf][nf], aH[mf], b[0], b[1]);
                }
            // pass 2: Ahi * Blo
            #pragma unroll
            for (int ng = 0; ng < 2; ng++) {
                uint32_t rb = (uint32_t)(b_r + ng * 16) * (RS * 2);
                LDSM_X4(bl[ng][0], bl[ng][1], bl[ng][2], bl[ng][3], BL + rb + bcol);
            }
            #pragma unroll
            for (int mf = 0; mf < 4; mf++)
                #pragma unroll
                for (int nf = 0; nf < 4; nf++) {
                    const uint32_t* b = bl[nf >> 1] + ((nf & 1) << 1);
                    MMA16816(acc[mf][nf], aH[mf], b[0], b[1]);
                }
            // pass 3: Alo * Bhi
            #pragma unroll
            for (int mf = 0; mf < 4; mf++) {
                uint32_t ra = (uint32_t)(a_r + mf * 16) * (RS * 2);
                LDSM_X4(aL[mf][0], aL[mf][1], aL[mf][2], aL[mf][3], AL + ra + acol);
            }
            #pragma unroll
            for (int mf = 0; mf < 4; mf++)
                #pragma unroll
                for (int nf = 0; nf < 4; nf++) {
                    const uint32_t* b = bh[nf >> 1] + ((nf & 1) << 1);
                    MMA16816(acc[mf][nf], aL[mf], b[0], b[1]);
                }
        }
    }

    // epilogue: fp32 + bias, float2 stores
    const int er = lane >> 2;          // 0..7
    const int ec = (lane & 3) << 1;    // 0,2,4,6
    #pragma unroll
    for (int mf = 0; mf < 4; mf++) {
        #pragma unroll
        for (int nf = 0; nf < 4; nf++) {
            int col  = n0 + wn * 32 + nf * 8 + ec;
            float bx = bias[col], by = bias[col + 1];
            int r0 = m0 + wm * 64 + mf * 16 + er;
            int r1 = r0 + 8;
            float2 o0 = make_float2(acc[mf][nf][0] + bx, acc[mf][nf][1] + by);
            float2 o1 = make_float2(acc[mf][nf][2] + bx, acc[mf][nf][3] + by);
            if (C_HM) {
                size_t base = (size_t)(col >> 6) * S;
                *(float2*)(C + (base + r0) * DH + (col & 63)) = o0;
                *(float2*)(C + (base + r1) * DH + (col & 63)) = o1;
            } else {
                *(float2*)(C + (size_t)r0 * N + col) = o0;
                *(float2*)(C + (size_t)r1 * N + col) = o1;
            }
        }
    }
}

// ---------------------------------------------------------------------------
// Causal flash attention (unchanged from R7 — known-good)
// ---------------------------------------------------------------------------
#define LDT 68
#define ATTN_SMEM (3 * 64 * LDT * 4)

__global__ __launch_bounds__(256) void attn_kernel(
    const float* __restrict__ Q, const float* __restrict__ K,
    const float* __restrict__ V, float* __restrict__ O, int S)
{
    extern __shared__ float smf[];
    float* Qt = smf;
    float* Kt = smf + 64 * LDT;
    float* Vs = smf + 2 * 64 * LDT;

    const int h  = blockIdx.y;
    const int i0 = blockIdx.x << 6;
    const float* Qh = Q + (size_t)h * S * DH;
    const float* Kh = K + (size_t)h * S * DH;
    const float* Vh = V + (size_t)h * S * DH;

    const int t  = threadIdx.x;
    const int tx = t & 15;
    const int ty = t >> 4;

    #pragma unroll
    for (int u = 0; u < 4; u++) {
        int idx = t + u * 256;
        int r  = idx & 63;
        int d4 = (idx >> 6) << 2;
        float4 qv = *(const float4*)(Qh + (size_t)(i0 + r) * DH + d4);
        Qt[(d4 + 0) * LDT + r] = qv.x;
        Qt[(d4 + 1) * LDT + r] = qv.y;
        Qt[(d4 + 2) * LDT + r] = qv.z;
        Qt[(d4 + 3) * LDT + r] = qv.w;
    }
    __syncthreads();

    float acc[4][4];
    float m_i[4], l_i[4];
    #pragma unroll
    for (int i = 0; i < 4; i++) {
        m_i[i] = -1e30f; l_i[i] = 0.0f;
        #pragma unroll
        for (int j = 0; j < 4; j++) acc[i][j] = 0.0f;
    }

    const int ntiles = blockIdx.x + 1;
    for (int jt = 0; jt < ntiles; jt++) {
        const int j0 = jt << 6;

        float4 kreg[4], vreg[4];
        #pragma unroll
        for (int u = 0; u < 4; u++) {
            int idx = t + u * 256;
            int rk = idx & 63;
            int d4 = (idx >> 6) << 2;
            kreg[u] = *(const float4*)(Kh + (size_t)(j0 + rk) * DH + d4);
            int rv = idx >> 4;
            int c4 = (idx & 15) << 2;
            vreg[u] = *(const float4*)(Vh + (size_t)(j0 + rv) * DH + c4);
        }
        __syncthreads();
        #pragma unroll
        for (int u = 0; u < 4; u++) {
            int idx = t + u * 256;
            int rk = idx & 63;
            int d4 = (idx >> 6) << 2;
            Kt[(d4 + 0) * LDT + rk] = kreg[u].x;
            Kt[(d4 + 1) * LDT + rk] = kreg[u].y;
            Kt[(d4 + 2) * LDT + rk] = kreg[u].z;
            Kt[(d4 + 3) * LDT + rk] = kreg[u].w;
            int rv = idx >> 4;
            int c4 = (idx & 15) << 2;
            *(float4*)(Vs + rv * LDT + c4) = vreg[u];
        }
        __syncthreads();

        float s[4][4];
        #pragma unroll
        for (int i = 0; i < 4; i++)
            #pragma unroll
            for (int j = 0; j < 4; j++) s[i][j] = 0.0f;

        #pragma unroll 8
        for (int d = 0; d < 64; d++) {
            float4 a4 = *(const float4*)(Qt + d * LDT + (ty << 2));
            float4 b4 = *(const float4*)(Kt + d * LDT + (tx << 2));
            float a[4] = {a4.x, a4.y, a4.z, a4.w};
            float b[4] = {b4.x, b4.y, b4.z, b4.w};
            #pragma unroll
            for (int i = 0; i < 4; i++)
                #pragma unroll
                for (int j = 0; j < 4; j++)
                    s[i][j] += a[i] * b[j];
        }

        const float scale = 0.125f;
        if (jt == blockIdx.x) {
            #pragma unroll
            for (int i = 0; i < 4; i++) {
                int qr = (ty << 2) + i;
                #pragma unroll
                for (int j = 0; j < 4; j++) {
                    int kc = (tx << 2) + j;
                    s[i][j] = (kc <= qr) ? s[i][j] * scale : -1e30f;
                }
            }
        } else {
            #pragma unroll
            for (int i = 0; i < 4; i++)
                #pragma unroll
                for (int j = 0; j < 4; j++) s[i][j] *= scale;
        }

        float mc[4];
        #pragma unroll
        for (int i = 0; i < 4; i++)
            mc[i] = fmaxf(fmaxf(s[i][0], s[i][1]), fmaxf(s[i][2], s[i][3]));
        #pragma unroll
        for (int off = 8; off; off >>= 1)
            #pragma unroll
            for (int i = 0; i < 4; i++)
                mc[i] = fmaxf(mc[i], __shfl_xor_sync(0xffffffffu, mc[i], off));

        float alpha[4];
        #pragma unroll
        for (int i = 0; i < 4; i++) {
            float mn = fmaxf(m_i[i], mc[i]);
            alpha[i] = __expf(m_i[i] - mn);
            m_i[i]   = mn;
        }

        float lc[4];
        #pragma unroll
        for (int i = 0; i < 4; i++) {
            #pragma unroll
            for (int j = 0; j < 4; j++) s[i][j] = __expf(s[i][j] - m_i[i]);
            lc[i] = (s[i][0] + s[i][1]) + (s[i][2] + s[i][3]);
        }
        #pragma unroll
        for (int off = 8; off; off >>= 1)
            #pragma unroll
            for (int i = 0; i < 4; i++)
                lc[i] += __shfl_xor_sync(0xffffffffu, lc[i], off);
        #pragma unroll
        for (int i = 0; i < 4; i++) {
            l_i[i] = l_i[i] * alpha[i] + lc[i];
            #pragma unroll
            for (int j = 0; j < 4; j++) acc[i][j] *= alpha[i];
        }

        __syncthreads();
        #pragma unroll
        for (int j = 0; j < 4; j++)
            *(float4*)(Kt + ((tx << 2) + j) * LDT + (ty << 2)) =
                make_float4(s[0][j], s[1][j], s[2][j], s[3][j]);
        __syncthreads();

        #pragma unroll 8
        for (int k = 0; k < 64; k++) {
            float4 a4 = *(const float4*)(Kt + k * LDT + (ty << 2));
            float4 b4 = *(const float4*)(Vs + k * LDT + (tx << 2));
            float a[4] = {a4.x, a4.y, a4.z, a4.w};
            float b[4] = {b4.x, b4.y, b4.z, b4.w};
            #pragma unroll
            for (int i = 0; i < 4; i++)
                #pragma unroll
                for (int j = 0; j < 4; j++)
                    acc[i][j] += a[i] * b[j];
        }
    }

    #pragma unroll
    for (int i = 0; i < 4; i++) {
        float inv = 1.0f / l_i[i];
        int r = i0 + (ty << 2) + i;
        float4 o = make_float4(acc[i][0] * inv, acc[i][1] * inv,
                               acc[i][2] * inv, acc[i][3] * inv);
        *(float4*)(O + ((size_t)h * S + r) * DH + (tx << 2)) = o;
    }
}

// ---------------------------------------------------------------------------
extern "C" void kernel_launch(void* const* d_in, const int* in_sizes, int n_in,
                              void* d_out, int out_size)
{
    const float* Xq = (const float*)d_in[0];
    const float* Xk = (const float*)d_in[1];
    const float* Xv = (const float*)d_in[2];
    const float* Wq = (const float*)d_in[3];
    const float* bq = (const float*)d_in[4];
    const float* Wk = (const float*)d_in[5];
    const float* bk = (const float*)d_in[6];
    const float* Wv = (const float*)d_in[7];
    const float* bv = (const float*)d_in[8];
    const float* Wo = (const float*)d_in[9];
    const float* bo = (const float*)d_in[10];
    float* out = (float*)d_out;

    const int S = in_sizes[0] / DD;   // 4096

    float *q, *k, *v, *ctx;
    cudaGetSymbolAddress((void**)&q,   g_q);
    cudaGetSymbolAddress((void**)&k,   g_k);
    cudaGetSymbolAddress((void**)&v,   g_v);
    cudaGetSymbolAddress((void**)&ctx, g_ctx);

    cudaFuncSetAttribute(attn_kernel,
                         cudaFuncAttributeMaxDynamicSharedMemorySize, ATTN_SMEM);

    dim3 gproj(DD / 128, S / 128);   // (8, 32)

    gemm_mma<0, 1><<<gproj, 256>>>(Xq, Wq, bq, q, DD, DD, S);
    gemm_mma<0, 1><<<gproj, 256>>>(Xk, Wk, bk, k, DD, DD, S);
    gemm_mma<0, 1><<<gproj, 256>>>(Xv, Wv, bv, v, DD, DD, S);

    attn_kernel<<<dim3(S / 64, HH), 256, ATTN_SMEM>>>(q, k, v, ctx, S);

    gemm_mma<1, 0><<<gproj, 256>>>(ctx, Wo, bo, out, DD, DD, S);
}

// round 10
// speedup vs baseline: 1.3484x; 1.0146x over previous
#include <cuda_runtime.h>
#include <cuda_bf16.h>
#include <cstdint>

#define HH   16
#define DH   64
#define DD   1024
#define SMAX 4096

// Scratch (allocation-free rule: __device__ globals). Head-major [H][S][64].
__device__ float g_q[HH * SMAX * DH];
__device__ float g_k[HH * SMAX * DH];
__device__ float g_v[HH * SMAX * DH];
__device__ float g_ctx[HH * SMAX * DH];

// ===========================================================================
// Warp-level tensor core primitives (baseline PTX, works on compute_103)
// ===========================================================================
__device__ __forceinline__ uint32_t smem_u32(const void* p) {
    uint32_t a;
    asm("{ .reg .u64 t; cvta.to.shared.u64 t, %1; cvt.u32.u64 %0, t; }"
        : "=r"(a) : "l"(p));
    return a;
}

#define LDSM_X4(r0, r1, r2, r3, addr)                                        \
    asm volatile("ldmatrix.sync.aligned.m8n8.x4.shared.b16 {%0,%1,%2,%3}, [%4];" \
                 : "=r"(r0), "=r"(r1), "=r"(r2), "=r"(r3) : "r"(addr))

#define MMA16816(d, a, b0, b1)                                               \
    asm volatile("mma.sync.aligned.m16n8k16.row.col.f32.bf16.bf16.f32 "     \
                 "{%0,%1,%2,%3}, {%4,%5,%6,%7}, {%8,%9}, {%0,%1,%2,%3};"    \
                 : "+f"((d)[0]), "+f"((d)[1]), "+f"((d)[2]), "+f"((d)[3])    \
                 : "r"((a)[0]), "r"((a)[1]), "r"((a)[2]), "r"((a)[3]),       \
                   "r"(b0), "r"(b1))

// Split float4 into bf16 hi + bf16 lo residual, packed as uint2 each.
__device__ __forceinline__ void split_bf16x3(float4 v, uint2& hv, uint2& lv) {
    __nv_bfloat162 h0 = __floats2bfloat162_rn(v.x, v.y);
    __nv_bfloat162 h1 = __floats2bfloat162_rn(v.z, v.w);
    float rx = v.x - __bfloat162float(h0.x);
    float ry = v.y - __bfloat162float(h0.y);
    float rz = v.z - __bfloat162float(h1.x);
    float rw = v.w - __bfloat162float(h1.y);
    __nv_bfloat162 l0 = __floats2bfloat162_rn(rx, ry);
    __nv_bfloat162 l1 = __floats2bfloat162_rn(rz, rw);
    hv = make_uint2(*reinterpret_cast<uint32_t*>(&h0),
                    *reinterpret_cast<uint32_t*>(&h1));
    lv = make_uint2(*reinterpret_cast<uint32_t*>(&l0),
                    *reinterpret_cast<uint32_t*>(&l1));
}

// ===========================================================================
// Tensor-core bf16x3 GEMM (NT): C[M,N] = A[M,K] * B[N,K]^T + bias[N]
// 128x128 CTA tile, BK=32, 8 warps (2M x 4N), warp tile 64x32.
// Smem rows stride 40 bf16 (80B) -> conflict-free ldmatrix, no swizzle.
// A_HM: A head-major [k>>6][m][k&63]; C_HM: C written head-major.
// ===========================================================================
#define RS    40                     // smem row stride in bf16 elems (80 B)
#define TOFF  (128 * RS)             // one 128x32 bf16 tile in elems

template<int A_HM, int C_HM>
__global__ __launch_bounds__(256) void gemm_mma(
    const float* __restrict__ A, const float* __restrict__ B,
    const float* __restrict__ bias, float* __restrict__ C,
    int N, int Kd, int S)
{
    __shared__ __nv_bfloat16 sh[4 * TOFF];   // Ah, Al, Bh, Bl = 40960 B
    const uint32_t sb = smem_u32(sh);
    const uint32_t AH = sb, AL = sb + TOFF * 2,
                   BH = sb + 2 * TOFF * 2, BL = sb + 3 * TOFF * 2;

    const int t    = threadIdx.x;
    const int lane = t & 31, wid = t >> 5;
    const int wm   = wid >> 2;        // 0..1  (64 rows each)
    const int wn   = wid & 3;         // 0..3  (32 cols each)
    const int m0   = blockIdx.y << 7, n0 = blockIdx.x << 7;

    // per-thread load mapping: 4 float4 for A, 4 for B per 128x32 chunk
    const int lrow = t >> 3;          // 0..31 (+32 per u)
    const int lc4  = (t & 7) << 2;    // 0,4,...,28

    // ldmatrix source addresses (byte): A frag rows, B frag rows
    const int a_r  = wm * 64 + (lane & 15);      // + mf*16
    const int a_c  = (lane >> 4) << 3;           // + ks*16
    const int b_g  = lane >> 3;                  // 0..3
    const int b_r  = wn * 32 + ((b_g >> 1) << 3) + (lane & 7);  // + ng*16
    const int b_c  = (b_g & 1) << 3;             // + ks*16

    float acc[4][4][4];
    #pragma unroll
    for (int i = 0; i < 4; i++)
        #pragma unroll
        for (int j = 0; j < 4; j++)
            #pragma unroll
            for (int r = 0; r < 4; r++) acc[i][j][r] = 0.0f;

    const int nch = Kd >> 5;          // 32 chunks of BK=32

    float4 av[4], bv[4];
    // preload chunk 0
    #pragma unroll
    for (int u = 0; u < 4; u++) {
        int row = lrow + (u << 5);
        if (A_HM)
            av[u] = *(const float4*)(A + (size_t)(m0 + row) * DH + lc4);
        else
            av[u] = *(const float4*)(A + (size_t)(m0 + row) * Kd + lc4);
        bv[u] = *(const float4*)(B + (size_t)(n0 + row) * Kd + lc4);
    }

    for (int i = 0; i < nch; i++) {
        __syncthreads();   // previous chunk's ldmatrix reads complete
        // convert + store chunk i
        #pragma unroll
        for (int u = 0; u < 4; u++) {
            int row = lrow + (u << 5);
            uint32_t eo = row * RS + lc4;
            uint2 hv, lv;
            split_bf16x3(av[u], hv, lv);
            *(uint2*)(sh + eo)            = hv;
            *(uint2*)(sh + TOFF + eo)     = lv;
            split_bf16x3(bv[u], hv, lv);
            *(uint2*)(sh + 2 * TOFF + eo) = hv;
            *(uint2*)(sh + 3 * TOFF + eo) = lv;
        }
        __syncthreads();

        // issue global loads for chunk i+1 (overlap with MMA below)
        if (i + 1 < nch) {
            const int k0 = (i + 1) << 5;
            #pragma unroll
            for (int u = 0; u < 4; u++) {
                int row = lrow + (u << 5);
                if (A_HM)
                    av[u] = *(const float4*)(A + ((size_t)(k0 >> 6) * S + m0 + row) * DH
                                               + (k0 & 63) + lc4);
                else
                    av[u] = *(const float4*)(A + (size_t)(m0 + row) * Kd + k0 + lc4);
                bv[u] = *(const float4*)(B + (size_t)(n0 + row) * Kd + k0 + lc4);
            }
        }

        // MMA on chunk i: 2 k16-steps x 3 bf16x3 passes
        #pragma unroll
        for (int ks = 0; ks < 2; ks++) {
            const uint32_t acol = (a_c + (ks << 4)) << 1;   // bytes
            const uint32_t bcol = (b_c + (ks << 4)) << 1;

            uint32_t aH[4][4], aL[4][4], bh[2][4], bl[2][4];
            #pragma unroll
            for (int mf = 0; mf < 4; mf++) {
                uint32_t ra = (uint32_t)(a_r + mf * 16) * (RS * 2);
                LDSM_X4(aH[mf][0], aH[mf][1], aH[mf][2], aH[mf][3], AH + ra + acol);
            }
            #pragma unroll
            for (int ng = 0; ng < 2; ng++) {
                uint32_t rb = (uint32_t)(b_r + ng * 16) * (RS * 2);
                LDSM_X4(bh[ng][0], bh[ng][1], bh[ng][2], bh[ng][3], BH + rb + bcol);
            }
            // pass 1: Ahi * Bhi
            #pragma unroll
            for (int mf = 0; mf < 4; mf++)
                #pragma unroll
                for (int nf = 0; nf < 4; nf++) {
                    const uint32_t* b = bh[nf >> 1] + ((nf & 1) << 1);
                    MMA16816(acc[mf][nf], aH[mf], b[0], b[1]);
                }
            // pass 2: Ahi * Blo
            #pragma unroll
            for (int ng = 0; ng < 2; ng++) {
                uint32_t rb = (uint32_t)(b_r + ng * 16) * (RS * 2);
                LDSM_X4(bl[ng][0], bl[ng][1], bl[ng][2], bl[ng][3], BL + rb + bcol);
            }
            #pragma unroll
            for (int mf = 0; mf < 4; mf++)
                #pragma unroll
                for (int nf = 0; nf < 4; nf++) {
                    const uint32_t* b = bl[nf >> 1] + ((nf & 1) << 1);
                    MMA16816(acc[mf][nf], aH[mf], b[0], b[1]);
                }
            // pass 3: Alo * Bhi
            #pragma unroll
            for (int mf = 0; mf < 4; mf++) {
                uint32_t ra = (uint32_t)(a_r + mf * 16) * (RS * 2);
                LDSM_X4(aL[mf][0], aL[mf][1], aL[mf][2], aL[mf][3], AL + ra + acol);
            }
            #pragma unroll
            for (int mf = 0; mf < 4; mf++)
                #pragma unroll
                for (int nf = 0; nf < 4; nf++) {
                    const uint32_t* b = bh[nf >> 1] + ((nf & 1) << 1);
                    MMA16816(acc[mf][nf], aL[mf], b[0], b[1]);
                }
        }
    }

    // epilogue: fp32 + bias, float2 stores
    const int er = lane >> 2;          // 0..7
    const int ec = (lane & 3) << 1;    // 0,2,4,6
    #pragma unroll
    for (int mf = 0; mf < 4; mf++) {
        #pragma unroll
        for (int nf = 0; nf < 4; nf++) {
            int col  = n0 + wn * 32 + nf * 8 + ec;
            float bx = bias[col], by = bias[col + 1];
            int r0 = m0 + wm * 64 + mf * 16 + er;
            int r1 = r0 + 8;
            float2 o0 = make_float2(acc[mf][nf][0] + bx, acc[mf][nf][1] + by);
            float2 o1 = make_float2(acc[mf][nf][2] + bx, acc[mf][nf][3] + by);
            if (C_HM) {
                size_t base = (size_t)(col >> 6) * S;
                *(float2*)(C + (base + r0) * DH + (col & 63)) = o0;
                *(float2*)(C + (base + r1) * DH + (col & 63)) = o1;
            } else {
                *(float2*)(C + (size_t)r0 * N + col) = o0;
                *(float2*)(C + (size_t)r1 * N + col) = o1;
            }
        }
    }
}

// ---------------------------------------------------------------------------
// Causal flash attention (unchanged from R7 — known-good)
// ---------------------------------------------------------------------------
#define LDT 68
#define ATTN_SMEM (3 * 64 * LDT * 4)

__global__ __launch_bounds__(256) void attn_kernel(
    const float* __restrict__ Q, const float* __restrict__ K,
    const float* __restrict__ V, float* __restrict__ O, int S)
{
    extern __shared__ float smf[];
    float* Qt = smf;
    float* Kt = smf + 64 * LDT;
    float* Vs = smf + 2 * 64 * LDT;

    const int h  = blockIdx.y;
    const int i0 = blockIdx.x << 6;
    const float* Qh = Q + (size_t)h * S * DH;
    const float* Kh = K + (size_t)h * S * DH;
    const float* Vh = V + (size_t)h * S * DH;

    const int t  = threadIdx.x;
    const int tx = t & 15;
    const int ty = t >> 4;

    #pragma unroll
    for (int u = 0; u < 4; u++) {
        int idx = t + u * 256;
        int r  = idx & 63;
        int d4 = (idx >> 6) << 2;
        float4 qv = *(const float4*)(Qh + (size_t)(i0 + r) * DH + d4);
        Qt[(d4 + 0) * LDT + r] = qv.x;
        Qt[(d4 + 1) * LDT + r] = qv.y;
        Qt[(d4 + 2) * LDT + r] = qv.z;
        Qt[(d4 + 3) * LDT + r] = qv.w;
    }
    __syncthreads();

    float acc[4][4];
    float m_i[4], l_i[4];
    #pragma unroll
    for (int i = 0; i < 4; i++) {
        m_i[i] = -1e30f; l_i[i] = 0.0f;
        #pragma unroll
        for (int j = 0; j < 4; j++) acc[i][j] = 0.0f;
    }

    const int ntiles = blockIdx.x + 1;
    for (int jt = 0; jt < ntiles; jt++) {
        const int j0 = jt << 6;

        float4 kreg[4], vreg[4];
        #pragma unroll
        for (int u = 0; u < 4; u++) {
            int idx = t + u * 256;
            int rk = idx & 63;
            int d4 = (idx >> 6) << 2;
            kreg[u] = *(const float4*)(Kh + (size_t)(j0 + rk) * DH + d4);
            int rv = idx >> 4;
            int c4 = (idx & 15) << 2;
            vreg[u] = *(const float4*)(Vh + (size_t)(j0 + rv) * DH + c4);
        }
        __syncthreads();
        #pragma unroll
        for (int u = 0; u < 4; u++) {
            int idx = t + u * 256;
            int rk = idx & 63;
            int d4 = (idx >> 6) << 2;
            Kt[(d4 + 0) * LDT + rk] = kreg[u].x;
            Kt[(d4 + 1) * LDT + rk] = kreg[u].y;
            Kt[(d4 + 2) * LDT + rk] = kreg[u].z;
            Kt[(d4 + 3) * LDT + rk] = kreg[u].w;
            int rv = idx >> 4;
            int c4 = (idx & 15) << 2;
            *(float4*)(Vs + rv * LDT + c4) = vreg[u];
        }
        __syncthreads();

        float s[4][4];
        #pragma unroll
        for (int i = 0; i < 4; i++)
            #pragma unroll
            for (int j = 0; j < 4; j++) s[i][j] = 0.0f;

        #pragma unroll 8
        for (int d = 0; d < 64; d++) {
            float4 a4 = *(const float4*)(Qt + d * LDT + (ty << 2));
            float4 b4 = *(const float4*)(Kt + d * LDT + (tx << 2));
            float a[4] = {a4.x, a4.y, a4.z, a4.w};
            float b[4] = {b4.x, b4.y, b4.z, b4.w};
            #pragma unroll
            for (int i = 0; i < 4; i++)
                #pragma unroll
                for (int j = 0; j < 4; j++)
                    s[i][j] += a[i] * b[j];
        }

        const float scale = 0.125f;
        if (jt == blockIdx.x) {
            #pragma unroll
            for (int i = 0; i < 4; i++) {
                int qr = (ty << 2) + i;
                #pragma unroll
                for (int j = 0; j < 4; j++) {
                    int kc = (tx << 2) + j;
                    s[i][j] = (kc <= qr) ? s[i][j] * scale : -1e30f;
                }
            }
        } else {
            #pragma unroll
            for (int i = 0; i < 4; i++)
                #pragma unroll
                for (int j = 0; j < 4; j++) s[i][j] *= scale;
        }

        float mc[4];
        #pragma unroll
        for (int i = 0; i < 4; i++)
            mc[i] = fmaxf(fmaxf(s[i][0], s[i][1]), fmaxf(s[i][2], s[i][3]));
        #pragma unroll
        for (int off = 8; off; off >>= 1)
            #pragma unroll
            for (int i = 0; i < 4; i++)
                mc[i] = fmaxf(mc[i], __shfl_xor_sync(0xffffffffu, mc[i], off));

        float alpha[4];
        #pragma unroll
        for (int i = 0; i < 4; i++) {
            float mn = fmaxf(m_i[i], mc[i]);
            alpha[i] = __expf(m_i[i] - mn);
            m_i[i]   = mn;
        }

        float lc[4];
        #pragma unroll
        for (int i = 0; i < 4; i++) {
            #pragma unroll
            for (int j = 0; j < 4; j++) s[i][j] = __expf(s[i][j] - m_i[i]);
            lc[i] = (s[i][0] + s[i][1]) + (s[i][2] + s[i][3]);
        }
        #pragma unroll
        for (int off = 8; off; off >>= 1)
            #pragma unroll
            for (int i = 0; i < 4; i++)
                lc[i] += __shfl_xor_sync(0xffffffffu, lc[i], off);
        #pragma unroll
        for (int i = 0; i < 4; i++) {
            l_i[i] = l_i[i] * alpha[i] + lc[i];
            #pragma unroll
            for (int j = 0; j < 4; j++) acc[i][j] *= alpha[i];
        }

        __syncthreads();
        #pragma unroll
        for (int j = 0; j < 4; j++)
            *(float4*)(Kt + ((tx << 2) + j) * LDT + (ty << 2)) =
                make_float4(s[0][j], s[1][j], s[2][j], s[3][j]);
        __syncthreads();

        #pragma unroll 8
        for (int k = 0; k < 64; k++) {
            float4 a4 = *(const float4*)(Kt + k * LDT + (ty << 2));
            float4 b4 = *(const float4*)(Vs + k * LDT + (tx << 2));
            float a[4] = {a4.x, a4.y, a4.z, a4.w};
            float b[4] = {b4.x, b4.y, b4.z, b4.w};
            #pragma unroll
            for (int i = 0; i < 4; i++)
                #pragma unroll
                for (int j = 0; j < 4; j++)
                    acc[i][j] += a[i] * b[j];
        }
    }

    #pragma unroll
    for (int i = 0; i < 4; i++) {
        float inv = 1.0f / l_i[i];
        int r = i0 + (ty << 2) + i;
        float4 o = make_float4(acc[i][0] * inv, acc[i][1] * inv,
                               acc[i][2] * inv, acc[i][3] * inv);
        *(float4*)(O + ((size_t)h * S + r) * DH + (tx << 2)) = o;
    }
}

// ---------------------------------------------------------------------------
extern "C" void kernel_launch(void* const* d_in, const int* in_sizes, int n_in,
                              void* d_out, int out_size)
{
    const float* Xq = (const float*)d_in[0];
    const float* Xk = (const float*)d_in[1];
    const float* Xv = (const float*)d_in[2];
    const float* Wq = (const float*)d_in[3];
    const float* bq = (const float*)d_in[4];
    const float* Wk = (const float*)d_in[5];
    const float* bk = (const float*)d_in[6];
    const float* Wv = (const float*)d_in[7];
    const float* bv = (const float*)d_in[8];
    const float* Wo = (const float*)d_in[9];
    const float* bo = (const float*)d_in[10];
    float* out = (float*)d_out;

    const int S = in_sizes[0] / DD;   // 4096

    float *q, *k, *v, *ctx;
    cudaGetSymbolAddress((void**)&q,   g_q);
    cudaGetSymbolAddress((void**)&k,   g_k);
    cudaGetSymbolAddress((void**)&v,   g_v);
    cudaGetSymbolAddress((void**)&ctx, g_ctx);

    cudaFuncSetAttribute(attn_kernel,
                         cudaFuncAttributeMaxDynamicSharedMemorySize, ATTN_SMEM);

    dim3 gproj(DD / 128, S / 128);   // (8, 32)

    gemm_mma<0, 1><<<gproj, 256>>>(Xq, Wq, bq, q, DD, DD, S);
    gemm_mma<0, 1><<<gproj, 256>>>(Xk, Wk, bk, k, DD, DD, S);
    gemm_mma<0, 1><<<gproj, 256>>>(Xv, Wv, bv, v, DD, DD, S);

    attn_kernel<<<dim3(S / 64, HH), 256, ATTN_SMEM>>>(q, k, v, ctx, S);

    gemm_mma<1, 0><<<gproj, 256>>>(ctx, Wo, bo, out, DD, DD, S);
}

// round 11
// speedup vs baseline: 3.0220x; 2.2412x over previous
#include <cuda_runtime.h>
#include <cuda_bf16.h>
#include <cstdint>

#define HH   16
#define DH   64
#define DD   1024
#define SMAX 4096

// Scratch (allocation-free rule: __device__ globals). Head-major [H][S][64].
__device__ float g_q[HH * SMAX * DH];
__device__ float g_k[HH * SMAX * DH];
__device__ float g_v[HH * SMAX * DH];
__device__ float g_ctx[HH * SMAX * DH];

// ===========================================================================
// Warp-level tensor core primitives (baseline PTX, works on compute_103)
// ===========================================================================
__device__ __forceinline__ uint32_t smem_u32(const void* p) {
    uint32_t a;
    asm("{ .reg .u64 t; cvta.to.shared.u64 t, %1; cvt.u32.u64 %0, t; }"
        : "=r"(a) : "l"(p));
    return a;
}

#define LDSM_X4(r0, r1, r2, r3, addr)                                        \
    asm volatile("ldmatrix.sync.aligned.m8n8.x4.shared.b16 {%0,%1,%2,%3}, [%4];" \
                 : "=r"(r0), "=r"(r1), "=r"(r2), "=r"(r3) : "r"(addr))

#define LDSM_X4_T(r0, r1, r2, r3, addr)                                      \
    asm volatile("ldmatrix.sync.aligned.m8n8.x4.trans.shared.b16 {%0,%1,%2,%3}, [%4];" \
                 : "=r"(r0), "=r"(r1), "=r"(r2), "=r"(r3) : "r"(addr))

#define MMA16816(d, a, b0, b1)                                               \
    asm volatile("mma.sync.aligned.m16n8k16.row.col.f32.bf16.bf16.f32 "     \
                 "{%0,%1,%2,%3}, {%4,%5,%6,%7}, {%8,%9}, {%0,%1,%2,%3};"    \
                 : "+f"((d)[0]), "+f"((d)[1]), "+f"((d)[2]), "+f"((d)[3])    \
                 : "r"((a)[0]), "r"((a)[1]), "r"((a)[2]), "r"((a)[3]),       \
                   "r"(b0), "r"(b1))

// Split float4 into bf16 hi + bf16 lo residual, packed as uint2 each.
__device__ __forceinline__ void split_bf16x3(float4 v, uint2& hv, uint2& lv) {
    __nv_bfloat162 h0 = __floats2bfloat162_rn(v.x, v.y);
    __nv_bfloat162 h1 = __floats2bfloat162_rn(v.z, v.w);
    float rx = v.x - __bfloat162float(h0.x);
    float ry = v.y - __bfloat162float(h0.y);
    float rz = v.z - __bfloat162float(h1.x);
    float rw = v.w - __bfloat162float(h1.y);
    __nv_bfloat162 l0 = __floats2bfloat162_rn(rx, ry);
    __nv_bfloat162 l1 = __floats2bfloat162_rn(rz, rw);
    hv = make_uint2(*reinterpret_cast<uint32_t*>(&h0),
                    *reinterpret_cast<uint32_t*>(&h1));
    lv = make_uint2(*reinterpret_cast<uint32_t*>(&l0),
                    *reinterpret_cast<uint32_t*>(&l1));
}

// ===========================================================================
// Tensor-core bf16x3 GEMM (NT): C[M,N] = A[M,K] * B[N,K]^T + bias[N]
// (unchanged from R10 — known-good)
// ===========================================================================
#define RS    40
#define TOFF  (128 * RS)

template<int A_HM, int C_HM>
__global__ __launch_bounds__(256) void gemm_mma(
    const float* __restrict__ A, const float* __restrict__ B,
    const float* __restrict__ bias, float* __restrict__ C,
    int N, int Kd, int S)
{
    __shared__ __nv_bfloat16 sh[4 * TOFF];
    const uint32_t sb = smem_u32(sh);
    const uint32_t AH = sb, AL = sb + TOFF * 2,
                   BH = sb + 2 * TOFF * 2, BL = sb + 3 * TOFF * 2;

    const int t    = threadIdx.x;
    const int lane = t & 31, wid = t >> 5;
    const int wm   = wid >> 2;
    const int wn   = wid & 3;
    const int m0   = blockIdx.y << 7, n0 = blockIdx.x << 7;

    const int lrow = t >> 3;
    const int lc4  = (t & 7) << 2;

    const int a_r  = wm * 64 + (lane & 15);
    const int a_c  = (lane >> 4) << 3;
    const int b_g  = lane >> 3;
    const int b_r  = wn * 32 + ((b_g >> 1) << 3) + (lane & 7);
    const int b_c  = (b_g & 1) << 3;

    float acc[4][4][4];
    #pragma unroll
    for (int i = 0; i < 4; i++)
        #pragma unroll
        for (int j = 0; j < 4; j++)
            #pragma unroll
            for (int r = 0; r < 4; r++) acc[i][j][r] = 0.0f;

    const int nch = Kd >> 5;

    float4 av[4], bv[4];
    #pragma unroll
    for (int u = 0; u < 4; u++) {
        int row = lrow + (u << 5);
        if (A_HM)
            av[u] = *(const float4*)(A + (size_t)(m0 + row) * DH + lc4);
        else
            av[u] = *(const float4*)(A + (size_t)(m0 + row) * Kd + lc4);
        bv[u] = *(const float4*)(B + (size_t)(n0 + row) * Kd + lc4);
    }

    for (int i = 0; i < nch; i++) {
        __syncthreads();
        #pragma unroll
        for (int u = 0; u < 4; u++) {
            int row = lrow + (u << 5);
            uint32_t eo = row * RS + lc4;
            uint2 hv, lv;
            split_bf16x3(av[u], hv, lv);
            *(uint2*)(sh + eo)            = hv;
            *(uint2*)(sh + TOFF + eo)     = lv;
            split_bf16x3(bv[u], hv, lv);
            *(uint2*)(sh + 2 * TOFF + eo) = hv;
            *(uint2*)(sh + 3 * TOFF + eo) = lv;
        }
        __syncthreads();

        if (i + 1 < nch) {
            const int k0 = (i + 1) << 5;
            #pragma unroll
            for (int u = 0; u < 4; u++) {
                int row = lrow + (u << 5);
                if (A_HM)
                    av[u] = *(const float4*)(A + ((size_t)(k0 >> 6) * S + m0 + row) * DH
                                               + (k0 & 63) + lc4);
                else
                    av[u] = *(const float4*)(A + (size_t)(m0 + row) * Kd + k0 + lc4);
                bv[u] = *(const float4*)(B + (size_t)(n0 + row) * Kd + k0 + lc4);
            }
        }

        #pragma unroll
        for (int ks = 0; ks < 2; ks++) {
            const uint32_t acol = (a_c + (ks << 4)) << 1;
            const uint32_t bcol = (b_c + (ks << 4)) << 1;

            uint32_t aH[4][4], aL[4][4], bh[2][4], bl[2][4];
            #pragma unroll
            for (int mf = 0; mf < 4; mf++) {
                uint32_t ra = (uint32_t)(a_r + mf * 16) * (RS * 2);
                LDSM_X4(aH[mf][0], aH[mf][1], aH[mf][2], aH[mf][3], AH + ra + acol);
            }
            #pragma unroll
            for (int ng = 0; ng < 2; ng++) {
                uint32_t rb = (uint32_t)(b_r + ng * 16) * (RS * 2);
                LDSM_X4(bh[ng][0], bh[ng][1], bh[ng][2], bh[ng][3], BH + rb + bcol);
            }
            #pragma unroll
            for (int mf = 0; mf < 4; mf++)
                #pragma unroll
                for (int nf = 0; nf < 4; nf++) {
                    const uint32_t* b = bh[nf >> 1] + ((nf & 1) << 1);
                    MMA16816(acc[mf][nf], aH[mf], b[0], b[1]);
                }
            #pragma unroll
            for (int ng = 0; ng < 2; ng++) {
                uint32_t rb = (uint32_t)(b_r + ng * 16) * (RS * 2);
                LDSM_X4(bl[ng][0], bl[ng][1], bl[ng][2], bl[ng][3], BL + rb + bcol);
            }
            #pragma unroll
            for (int mf = 0; mf < 4; mf++)
                #pragma unroll
                for (int nf = 0; nf < 4; nf++) {
                    const uint32_t* b = bl[nf >> 1] + ((nf & 1) << 1);
                    MMA16816(acc[mf][nf], aH[mf], b[0], b[1]);
                }
            #pragma unroll
            for (int mf = 0; mf < 4; mf++) {
                uint32_t ra = (uint32_t)(a_r + mf * 16) * (RS * 2);
                LDSM_X4(aL[mf][0], aL[mf][1], aL[mf][2], aL[mf][3], AL + ra + acol);
            }
            #pragma unroll
            for (int mf = 0; mf < 4; mf++)
                #pragma unroll
                for (int nf = 0; nf < 4; nf++) {
                    const uint32_t* b = bh[nf >> 1] + ((nf & 1) << 1);
                    MMA16816(acc[mf][nf], aL[mf], b[0], b[1]);
                }
        }
    }

    const int er = lane >> 2;
    const int ec = (lane & 3) << 1;
    #pragma unroll
    for (int mf = 0; mf < 4; mf++) {
        #pragma unroll
        for (int nf = 0; nf < 4; nf++) {
            int col  = n0 + wn * 32 + nf * 8 + ec;
            float bx = bias[col], by = bias[col + 1];
            int r0 = m0 + wm * 64 + mf * 16 + er;
            int r1 = r0 + 8;
            float2 o0 = make_float2(acc[mf][nf][0] + bx, acc[mf][nf][1] + by);
            float2 o1 = make_float2(acc[mf][nf][2] + bx, acc[mf][nf][3] + by);
            if (C_HM) {
                size_t base = (size_t)(col >> 6) * S;
                *(float2*)(C + (base + r0) * DH + (col & 63)) = o0;
                *(float2*)(C + (base + r1) * DH + (col & 63)) = o1;
            } else {
                *(float2*)(C + (size_t)r0 * N + col) = o0;
                *(float2*)(C + (size_t)r1 * N + col) = o1;
            }
        }
    }
}

// ===========================================================================
// Tensor-core causal flash attention (bf16x3). One CTA = (head, 128 q rows),
// 8 warps, warp w owns rows [w*16, w*16+16). kv tiles of 64.
// Q/K/V hi+lo bf16 in smem, stride 72 elems (144 B -> conflict-free ldmatrix).
// P fragments built in registers from the S accumulators (no smem round-trip).
// ===========================================================================
#define ARS   72
#define QHo   0
#define QLo   9216
#define KHo   18432
#define KLo   23040
#define VHo   27648
#define VLo   32256
#define ATTN_SMEM (36864 * 2)

__global__ __launch_bounds__(256) void attn_mma(
    const float* __restrict__ Q, const float* __restrict__ K,
    const float* __restrict__ V, float* __restrict__ O, int S)
{
    extern __shared__ __nv_bfloat16 sh[];
    const uint32_t sb = smem_u32(sh);

    const int h  = blockIdx.y;
    const int bq = blockIdx.x;
    const int i0 = bq << 7;
    const float* Qh = Q + (size_t)h * S * DH;
    const float* Kh = K + (size_t)h * S * DH;
    const float* Vh = V + (size_t)h * S * DH;

    const int t = threadIdx.x, lane = t & 31, w = t >> 5;

    // ---- stage Q (128x64) as hi/lo bf16 ----
    #pragma unroll
    for (int u = 0; u < 8; u++) {
        int idx = t + u * 256;
        int row = idx >> 4;
        int c4  = (idx & 15) << 2;
        float4 qv = *(const float4*)(Qh + (size_t)(i0 + row) * DH + c4);
        uint2 hv, lv;
        split_bf16x3(qv, hv, lv);
        *(uint2*)(sh + QHo + row * ARS + c4) = hv;
        *(uint2*)(sh + QLo + row * ARS + c4) = lv;
    }
    __syncthreads();

    // ---- Q fragments (held in registers for the whole kernel) ----
    uint32_t qhi[4][4], qlo[4][4];
    {
        const uint32_t ar = (uint32_t)(w * 16 + (lane & 15)) * (ARS * 2);
        const uint32_t ac = ((lane >> 4) << 3) * 2;
        #pragma unroll
        for (int ks = 0; ks < 4; ks++) {
            LDSM_X4(qhi[ks][0], qhi[ks][1], qhi[ks][2], qhi[ks][3],
                    sb + QHo * 2 + ar + ac + ks * 32);
            LDSM_X4(qlo[ks][0], qlo[ks][1], qlo[ks][2], qlo[ks][3],
                    sb + QLo * 2 + ar + ac + ks * 32);
        }
    }

    float oacc[8][4];
    #pragma unroll
    for (int nf = 0; nf < 8; nf++)
        #pragma unroll
        for (int e = 0; e < 4; e++) oacc[nf][e] = 0.0f;
    float m0 = -1e30f, m1 = -1e30f, l0 = 0.0f, l1 = 0.0f;

    // ldmatrix address components
    const int g    = lane >> 3;
    const uint32_t kb_r = ((g >> 1) << 3) + (lane & 7);   // K frag: n-row
    const uint32_t kb_c = ((g & 1) << 3) * 2;             // K frag: k-col bytes
    const uint32_t vb_r = ((g & 1) << 3) + (lane & 7);    // V frag: k-row
    const uint32_t vb_c = ((g >> 1) << 3) * 2;            // V frag: n-col bytes

    const int row_lo = w * 16 + (lane >> 2);              // block-local rows
    const int n_tiles = 2 * (bq + 1);

    for (int jt = 0; jt < n_tiles; jt++) {
        const int j0 = jt << 6;

        // ---- stage K,V tile (64x64 each) ----
        float4 kv4[4], vv4[4];
        #pragma unroll
        for (int u = 0; u < 4; u++) {
            int idx = t + u * 256;
            int row = idx >> 4;
            int c4  = (idx & 15) << 2;
            kv4[u] = *(const float4*)(Kh + (size_t)(j0 + row) * DH + c4);
            vv4[u] = *(const float4*)(Vh + (size_t)(j0 + row) * DH + c4);
        }
        __syncthreads();   // previous tile's ldmatrix reads complete
        #pragma unroll
        for (int u = 0; u < 4; u++) {
            int idx = t + u * 256;
            int row = idx >> 4;
            int c4  = (idx & 15) << 2;
            uint2 hv, lv;
            split_bf16x3(kv4[u], hv, lv);
            *(uint2*)(sh + KHo + row * ARS + c4) = hv;
            *(uint2*)(sh + KLo + row * ARS + c4) = lv;
            split_bf16x3(vv4[u], hv, lv);
            *(uint2*)(sh + VHo + row * ARS + c4) = hv;
            *(uint2*)(sh + VLo + row * ARS + c4) = lv;
        }
        __syncthreads();

        // fully-masked tile for this warp -> skip compute (syncs already done)
        if (j0 > i0 + w * 16 + 15) continue;

        // ---- S = Q K^T (bf16x3, 3 passes) ----
        float sacc[8][4];
        #pragma unroll
        for (int nf = 0; nf < 8; nf++)
            #pragma unroll
            for (int e = 0; e < 4; e++) sacc[nf][e] = 0.0f;

        #pragma unroll
        for (int ks = 0; ks < 4; ks++) {
            uint32_t kb[4][4];
            #pragma unroll
            for (int kg = 0; kg < 4; kg++)
                LDSM_X4(kb[kg][0], kb[kg][1], kb[kg][2], kb[kg][3],
                        sb + KHo * 2 + (kg * 16 + kb_r) * (ARS * 2) + ks * 32 + kb_c);
            #pragma unroll
            for (int nf = 0; nf < 8; nf++) {
                const uint32_t* b = kb[nf >> 1] + ((nf & 1) << 1);
                MMA16816(sacc[nf], qhi[ks], b[0], b[1]);
            }
            #pragma unroll
            for (int nf = 0; nf < 8; nf++) {
                const uint32_t* b = kb[nf >> 1] + ((nf & 1) << 1);
                MMA16816(sacc[nf], qlo[ks], b[0], b[1]);
            }
            #pragma unroll
            for (int kg = 0; kg < 4; kg++)
                LDSM_X4(kb[kg][0], kb[kg][1], kb[kg][2], kb[kg][3],
                        sb + KLo * 2 + (kg * 16 + kb_r) * (ARS * 2) + ks * 32 + kb_c);
            #pragma unroll
            for (int nf = 0; nf < 8; nf++) {
                const uint32_t* b = kb[nf >> 1] + ((nf & 1) << 1);
                MMA16816(sacc[nf], qhi[ks], b[0], b[1]);
            }
        }

        // ---- softmax update ----
        const bool needmask = (j0 + 63 > i0 + w * 16);
        #pragma unroll
        for (int nf = 0; nf < 8; nf++) {
            #pragma unroll
            for (int e = 0; e < 4; e++) {
                float v = sacc[nf][e] * 0.125f;
                if (needmask) {
                    int col = j0 + nf * 8 + ((lane & 3) << 1) + (e & 1);
                    int row = i0 + row_lo + ((e >> 1) << 3);
                    if (col > row) v = -1e30f;
                }
                sacc[nf][e] = v;
            }
        }
        float mt0 = -1e30f, mt1 = -1e30f;
        #pragma unroll
        for (int nf = 0; nf < 8; nf++) {
            mt0 = fmaxf(mt0, fmaxf(sacc[nf][0], sacc[nf][1]));
            mt1 = fmaxf(mt1, fmaxf(sacc[nf][2], sacc[nf][3]));
        }
        mt0 = fmaxf(mt0, __shfl_xor_sync(0xffffffffu, mt0, 1));
        mt0 = fmaxf(mt0, __shfl_xor_sync(0xffffffffu, mt0, 2));
        mt1 = fmaxf(mt1, __shfl_xor_sync(0xffffffffu, mt1, 1));
        mt1 = fmaxf(mt1, __shfl_xor_sync(0xffffffffu, mt1, 2));

        float mn0 = fmaxf(m0, mt0), mn1 = fmaxf(m1, mt1);
        float a0 = __expf(m0 - mn0), a1 = __expf(m1 - mn1);
        m0 = mn0; m1 = mn1;

        float s0 = 0.0f, s1 = 0.0f;
        #pragma unroll
        for (int nf = 0; nf < 8; nf++) {
            sacc[nf][0] = __expf(sacc[nf][0] - m0);
            sacc[nf][1] = __expf(sacc[nf][1] - m0);
            sacc[nf][2] = __expf(sacc[nf][2] - m1);
            sacc[nf][3] = __expf(sacc[nf][3] - m1);
            s0 += sacc[nf][0] + sacc[nf][1];
            s1 += sacc[nf][2] + sacc[nf][3];
        }
        s0 += __shfl_xor_sync(0xffffffffu, s0, 1);
        s0 += __shfl_xor_sync(0xffffffffu, s0, 2);
        s1 += __shfl_xor_sync(0xffffffffu, s1, 1);
        s1 += __shfl_xor_sync(0xffffffffu, s1, 2);
        l0 = l0 * a0 + s0;
        l1 = l1 * a1 + s1;
        #pragma unroll
        for (int nf = 0; nf < 8; nf++) {
            oacc[nf][0] *= a0; oacc[nf][1] *= a0;
            oacc[nf][2] *= a1; oacc[nf][3] *= a1;
        }

        // ---- O += P V (bf16x3; P frags straight from registers) ----
        #pragma unroll
        for (int ks = 0; ks < 4; ks++) {
            uint32_t phi[4], plo[4];
            #pragma unroll
            for (int half = 0; half < 2; half++) {
                const float* p = sacc[2 * ks + half];
                __nv_bfloat162 h01 = __floats2bfloat162_rn(p[0], p[1]);
                __nv_bfloat162 h23 = __floats2bfloat162_rn(p[2], p[3]);
                __nv_bfloat162 l01 = __floats2bfloat162_rn(
                    p[0] - __bfloat162float(h01.x), p[1] - __bfloat162float(h01.y));
                __nv_bfloat162 l23 = __floats2bfloat162_rn(
                    p[2] - __bfloat162float(h23.x), p[3] - __bfloat162float(h23.y));
                phi[half * 2 + 0] = *reinterpret_cast<uint32_t*>(&h01);
                phi[half * 2 + 1] = *reinterpret_cast<uint32_t*>(&h23);
                plo[half * 2 + 0] = *reinterpret_cast<uint32_t*>(&l01);
                plo[half * 2 + 1] = *reinterpret_cast<uint32_t*>(&l23);
            }
            // wait: a-frag order must be {(r,k0),(r+8,k0),(r,k8),(r+8,k8)}
            // half0 gives (r,k0..1 block)=h01? h01 packs p[0],p[1] = (r, cols)
            // and h23 = (r+8). half1 = k+8 halves. Order already correct:
            // phi = { (r,klo), (r+8,klo), (r,khi), (r+8,khi) }  ✓
            uint32_t vb[4][4];
            #pragma unroll
            for (int kg = 0; kg < 4; kg++)
                LDSM_X4_T(vb[kg][0], vb[kg][1], vb[kg][2], vb[kg][3],
                          sb + VHo * 2 + (ks * 16 + vb_r) * (ARS * 2) + kg * 32 + vb_c);
            #pragma unroll
            for (int nf = 0; nf < 8; nf++) {
                const uint32_t* b = vb[nf >> 1] + ((nf & 1) << 1);
                MMA16816(oacc[nf], phi, b[0], b[1]);
            }
            #pragma unroll
            for (int nf = 0; nf < 8; nf++) {
                const uint32_t* b = vb[nf >> 1] + ((nf & 1) << 1);
                MMA16816(oacc[nf], plo, b[0], b[1]);
            }
            #pragma unroll
            for (int kg = 0; kg < 4; kg++)
                LDSM_X4_T(vb[kg][0], vb[kg][1], vb[kg][2], vb[kg][3],
                          sb + VLo * 2 + (ks * 16 + vb_r) * (ARS * 2) + kg * 32 + vb_c);
            #pragma unroll
            for (int nf = 0; nf < 8; nf++) {
                const uint32_t* b = vb[nf >> 1] + ((nf & 1) << 1);
                MMA16816(oacc[nf], phi, b[0], b[1]);
            }
        }
    }

    // ---- normalize + store ----
    const float inv0 = 1.0f / l0, inv1 = 1.0f / l1;
    const int r0 = i0 + row_lo;
    #pragma unroll
    for (int nf = 0; nf < 8; nf++) {
        int col = nf * 8 + ((lane & 3) << 1);
        *(float2*)(O + ((size_t)h * S + r0) * DH + col) =
            make_float2(oacc[nf][0] * inv0, oacc[nf][1] * inv0);
        *(float2*)(O + ((size_t)h * S + r0 + 8) * DH + col) =
            make_float2(oacc[nf][2] * inv1, oacc[nf][3] * inv1);
    }
}

// ---------------------------------------------------------------------------
extern "C" void kernel_launch(void* const* d_in, const int* in_sizes, int n_in,
                              void* d_out, int out_size)
{
    const float* Xq = (const float*)d_in[0];
    const float* Xk = (const float*)d_in[1];
    const float* Xv = (const float*)d_in[2];
    const float* Wq = (const float*)d_in[3];
    const float* bq = (const float*)d_in[4];
    const float* Wk = (const float*)d_in[5];
    const float* bk = (const float*)d_in[6];
    const float* Wv = (const float*)d_in[7];
    const float* bv = (const float*)d_in[8];
    const float* Wo = (const float*)d_in[9];
    const float* bo = (const float*)d_in[10];
    float* out = (float*)d_out;

    const int S = in_sizes[0] / DD;   // 4096

    float *q, *k, *v, *ctx;
    cudaGetSymbolAddress((void**)&q,   g_q);
    cudaGetSymbolAddress((void**)&k,   g_k);
    cudaGetSymbolAddress((void**)&v,   g_v);
    cudaGetSymbolAddress((void**)&ctx, g_ctx);

    cudaFuncSetAttribute(attn_mma,
                         cudaFuncAttributeMaxDynamicSharedMemorySize, ATTN_SMEM);

    dim3 gproj(DD / 128, S / 128);   // (8, 32)

    gemm_mma<0, 1><<<gproj, 256>>>(Xq, Wq, bq, q, DD, DD, S);
    gemm_mma<0, 1><<<gproj, 256>>>(Xk, Wk, bk, k, DD, DD, S);
    gemm_mma<0, 1><<<gproj, 256>>>(Xv, Wv, bv, v, DD, DD, S);

    attn_mma<<<dim3(S / 128, HH), 256, ATTN_SMEM>>>(q, k, v, ctx, S);

    gemm_mma<1, 0><<<gproj, 256>>>(ctx, Wo, bo, out, DD, DD, S);
}

// round 12
// speedup vs baseline: 3.0233x; 1.0004x over previous
#include <cuda_runtime.h>
#include <cuda_bf16.h>
#include <cstdint>

#define HH   16
#define DH   64
#define DD   1024
#define SMAX 4096

// Scratch (allocation-free rule: __device__ globals). Head-major [H][S][64].
__device__ float g_q[HH * SMAX * DH];
__device__ float g_k[HH * SMAX * DH];
__device__ float g_v[HH * SMAX * DH];
__device__ float g_ctx[HH * SMAX * DH];

// ===========================================================================
// Warp-level tensor core primitives (baseline PTX, works on compute_103)
// ===========================================================================
__device__ __forceinline__ uint32_t smem_u32(const void* p) {
    uint32_t a;
    asm("{ .reg .u64 t; cvta.to.shared.u64 t, %1; cvt.u32.u64 %0, t; }"
        : "=r"(a) : "l"(p));
    return a;
}

#define LDSM_X4(r0, r1, r2, r3, addr)                                        \
    asm volatile("ldmatrix.sync.aligned.m8n8.x4.shared.b16 {%0,%1,%2,%3}, [%4];" \
                 : "=r"(r0), "=r"(r1), "=r"(r2), "=r"(r3) : "r"(addr))

#define LDSM_X4_T(r0, r1, r2, r3, addr)                                      \
    asm volatile("ldmatrix.sync.aligned.m8n8.x4.trans.shared.b16 {%0,%1,%2,%3}, [%4];" \
                 : "=r"(r0), "=r"(r1), "=r"(r2), "=r"(r3) : "r"(addr))

#define MMA16816(d, a, b0, b1)                                               \
    asm volatile("mma.sync.aligned.m16n8k16.row.col.f32.bf16.bf16.f32 "     \
                 "{%0,%1,%2,%3}, {%4,%5,%6,%7}, {%8,%9}, {%0,%1,%2,%3};"    \
                 : "+f"((d)[0]), "+f"((d)[1]), "+f"((d)[2]), "+f"((d)[3])    \
                 : "r"((a)[0]), "r"((a)[1]), "r"((a)[2]), "r"((a)[3]),       \
                   "r"(b0), "r"(b1))

// Split float4 into bf16 hi + bf16 lo residual, packed as uint2 each.
__device__ __forceinline__ void split_bf16x3(float4 v, uint2& hv, uint2& lv) {
    __nv_bfloat162 h0 = __floats2bfloat162_rn(v.x, v.y);
    __nv_bfloat162 h1 = __floats2bfloat162_rn(v.z, v.w);
    float rx = v.x - __bfloat162float(h0.x);
    float ry = v.y - __bfloat162float(h0.y);
    float rz = v.z - __bfloat162float(h1.x);
    float rw = v.w - __bfloat162float(h1.y);
    __nv_bfloat162 l0 = __floats2bfloat162_rn(rx, ry);
    __nv_bfloat162 l1 = __floats2bfloat162_rn(rz, rw);
    hv = make_uint2(*reinterpret_cast<uint32_t*>(&h0),
                    *reinterpret_cast<uint32_t*>(&h1));
    lv = make_uint2(*reinterpret_cast<uint32_t*>(&l0),
                    *reinterpret_cast<uint32_t*>(&l1));
}

// ===========================================================================
// Tensor-core bf16x3 GEMM (NT): C[M,N] = A[M,K] * B[N,K]^T + bias[N]
// (unchanged from R10 — known-good)
// ===========================================================================
#define RS    40
#define TOFF  (128 * RS)

template<int A_HM, int C_HM>
__global__ __launch_bounds__(256) void gemm_mma(
    const float* __restrict__ A, const float* __restrict__ B,
    const float* __restrict__ bias, float* __restrict__ C,
    int N, int Kd, int S)
{
    __shared__ __nv_bfloat16 sh[4 * TOFF];
    const uint32_t sb = smem_u32(sh);
    const uint32_t AH = sb, AL = sb + TOFF * 2,
                   BH = sb + 2 * TOFF * 2, BL = sb + 3 * TOFF * 2;

    const int t    = threadIdx.x;
    const int lane = t & 31, wid = t >> 5;
    const int wm   = wid >> 2;
    const int wn   = wid & 3;
    const int m0   = blockIdx.y << 7, n0 = blockIdx.x << 7;

    const int lrow = t >> 3;
    const int lc4  = (t & 7) << 2;

    const int a_r  = wm * 64 + (lane & 15);
    const int a_c  = (lane >> 4) << 3;
    const int b_g  = lane >> 3;
    const int b_r  = wn * 32 + ((b_g >> 1) << 3) + (lane & 7);
    const int b_c  = (b_g & 1) << 3;

    float acc[4][4][4];
    #pragma unroll
    for (int i = 0; i < 4; i++)
        #pragma unroll
        for (int j = 0; j < 4; j++)
            #pragma unroll
            for (int r = 0; r < 4; r++) acc[i][j][r] = 0.0f;

    const int nch = Kd >> 5;

    float4 av[4], bv[4];
    #pragma unroll
    for (int u = 0; u < 4; u++) {
        int row = lrow + (u << 5);
        if (A_HM)
            av[u] = *(const float4*)(A + (size_t)(m0 + row) * DH + lc4);
        else
            av[u] = *(const float4*)(A + (size_t)(m0 + row) * Kd + lc4);
        bv[u] = *(const float4*)(B + (size_t)(n0 + row) * Kd + lc4);
    }

    for (int i = 0; i < nch; i++) {
        __syncthreads();
        #pragma unroll
        for (int u = 0; u < 4; u++) {
            int row = lrow + (u << 5);
            uint32_t eo = row * RS + lc4;
            uint2 hv, lv;
            split_bf16x3(av[u], hv, lv);
            *(uint2*)(sh + eo)            = hv;
            *(uint2*)(sh + TOFF + eo)     = lv;
            split_bf16x3(bv[u], hv, lv);
            *(uint2*)(sh + 2 * TOFF + eo) = hv;
            *(uint2*)(sh + 3 * TOFF + eo) = lv;
        }
        __syncthreads();

        if (i + 1 < nch) {
            const int k0 = (i + 1) << 5;
            #pragma unroll
            for (int u = 0; u < 4; u++) {
                int row = lrow + (u << 5);
                if (A_HM)
                    av[u] = *(const float4*)(A + ((size_t)(k0 >> 6) * S + m0 + row) * DH
                                               + (k0 & 63) + lc4);
                else
                    av[u] = *(const float4*)(A + (size_t)(m0 + row) * Kd + k0 + lc4);
                bv[u] = *(const float4*)(B + (size_t)(n0 + row) * Kd + k0 + lc4);
            }
        }

        #pragma unroll
        for (int ks = 0; ks < 2; ks++) {
            const uint32_t acol = (a_c + (ks << 4)) << 1;
            const uint32_t bcol = (b_c + (ks << 4)) << 1;

            uint32_t aH[4][4], aL[4][4], bh[2][4], bl[2][4];
            #pragma unroll
            for (int mf = 0; mf < 4; mf++) {
                uint32_t ra = (uint32_t)(a_r + mf * 16) * (RS * 2);
                LDSM_X4(aH[mf][0], aH[mf][1], aH[mf][2], aH[mf][3], AH + ra + acol);
            }
            #pragma unroll
            for (int ng = 0; ng < 2; ng++) {
                uint32_t rb = (uint32_t)(b_r + ng * 16) * (RS * 2);
                LDSM_X4(bh[ng][0], bh[ng][1], bh[ng][2], bh[ng][3], BH + rb + bcol);
            }
            #pragma unroll
            for (int mf = 0; mf < 4; mf++)
                #pragma unroll
                for (int nf = 0; nf < 4; nf++) {
                    const uint32_t* b = bh[nf >> 1] + ((nf & 1) << 1);
                    MMA16816(acc[mf][nf], aH[mf], b[0], b[1]);
                }
            #pragma unroll
            for (int ng = 0; ng < 2; ng++) {
                uint32_t rb = (uint32_t)(b_r + ng * 16) * (RS * 2);
                LDSM_X4(bl[ng][0], bl[ng][1], bl[ng][2], bl[ng][3], BL + rb + bcol);
            }
            #pragma unroll
            for (int mf = 0; mf < 4; mf++)
                #pragma unroll
                for (int nf = 0; nf < 4; nf++) {
                    const uint32_t* b = bl[nf >> 1] + ((nf & 1) << 1);
                    MMA16816(acc[mf][nf], aH[mf], b[0], b[1]);
                }
            #pragma unroll
            for (int mf = 0; mf < 4; mf++) {
                uint32_t ra = (uint32_t)(a_r + mf * 16) * (RS * 2);
                LDSM_X4(aL[mf][0], aL[mf][1], aL[mf][2], aL[mf][3], AL + ra + acol);
            }
            #pragma unroll
            for (int mf = 0; mf < 4; mf++)
                #pragma unroll
                for (int nf = 0; nf < 4; nf++) {
                    const uint32_t* b = bh[nf >> 1] + ((nf & 1) << 1);
                    MMA16816(acc[mf][nf], aL[mf], b[0], b[1]);
                }
        }
    }

    const int er = lane >> 2;
    const int ec = (lane & 3) << 1;
    #pragma unroll
    for (int mf = 0; mf < 4; mf++) {
        #pragma unroll
        for (int nf = 0; nf < 4; nf++) {
            int col  = n0 + wn * 32 + nf * 8 + ec;
            float bx = bias[col], by = bias[col + 1];
            int r0 = m0 + wm * 64 + mf * 16 + er;
            int r1 = r0 + 8;
            float2 o0 = make_float2(acc[mf][nf][0] + bx, acc[mf][nf][1] + by);
            float2 o1 = make_float2(acc[mf][nf][2] + bx, acc[mf][nf][3] + by);
            if (C_HM) {
                size_t base = (size_t)(col >> 6) * S;
                *(float2*)(C + (base + r0) * DH + (col & 63)) = o0;
                *(float2*)(C + (base + r1) * DH + (col & 63)) = o1;
            } else {
                *(float2*)(C + (size_t)r0 * N + col) = o0;
                *(float2*)(C + (size_t)r1 * N + col) = o1;
            }
        }
    }
}

// ===========================================================================
// Tensor-core causal flash attention (bf16x3). One CTA = (head, 128 q rows),
// 8 warps, warp w owns rows [w*16, w*16+16). kv tiles of 64.
// Q/K/V hi+lo bf16 in smem, stride 72 elems (144 B -> conflict-free ldmatrix).
// P fragments built in registers from the S accumulators (no smem round-trip).
// ===========================================================================
#define ARS   72
#define QHo   0
#define QLo   9216
#define KHo   18432
#define KLo   23040
#define VHo   27648
#define VLo   32256
#define ATTN_SMEM (36864 * 2)

__global__ __launch_bounds__(256) void attn_mma(
    const float* __restrict__ Q, const float* __restrict__ K,
    const float* __restrict__ V, float* __restrict__ O, int S)
{
    extern __shared__ __nv_bfloat16 sh[];
    const uint32_t sb = smem_u32(sh);

    const int h  = blockIdx.y;
    const int bq = blockIdx.x;
    const int i0 = bq << 7;
    const float* Qh = Q + (size_t)h * S * DH;
    const float* Kh = K + (size_t)h * S * DH;
    const float* Vh = V + (size_t)h * S * DH;

    const int t = threadIdx.x, lane = t & 31, w = t >> 5;

    // ---- stage Q (128x64) as hi/lo bf16 ----
    #pragma unroll
    for (int u = 0; u < 8; u++) {
        int idx = t + u * 256;
        int row = idx >> 4;
        int c4  = (idx & 15) << 2;
        float4 qv = *(const float4*)(Qh + (size_t)(i0 + row) * DH + c4);
        uint2 hv, lv;
        split_bf16x3(qv, hv, lv);
        *(uint2*)(sh + QHo + row * ARS + c4) = hv;
        *(uint2*)(sh + QLo + row * ARS + c4) = lv;
    }
    __syncthreads();

    // ---- Q fragments (held in registers for the whole kernel) ----
    uint32_t qhi[4][4], qlo[4][4];
    {
        const uint32_t ar = (uint32_t)(w * 16 + (lane & 15)) * (ARS * 2);
        const uint32_t ac = ((lane >> 4) << 3) * 2;
        #pragma unroll
        for (int ks = 0; ks < 4; ks++) {
            LDSM_X4(qhi[ks][0], qhi[ks][1], qhi[ks][2], qhi[ks][3],
                    sb + QHo * 2 + ar + ac + ks * 32);
            LDSM_X4(qlo[ks][0], qlo[ks][1], qlo[ks][2], qlo[ks][3],
                    sb + QLo * 2 + ar + ac + ks * 32);
        }
    }

    float oacc[8][4];
    #pragma unroll
    for (int nf = 0; nf < 8; nf++)
        #pragma unroll
        for (int e = 0; e < 4; e++) oacc[nf][e] = 0.0f;
    float m0 = -1e30f, m1 = -1e30f, l0 = 0.0f, l1 = 0.0f;

    // ldmatrix address components
    const int g    = lane >> 3;
    const uint32_t kb_r = ((g >> 1) << 3) + (lane & 7);   // K frag: n-row
    const uint32_t kb_c = ((g & 1) << 3) * 2;             // K frag: k-col bytes
    const uint32_t vb_r = ((g & 1) << 3) + (lane & 7);    // V frag: k-row
    const uint32_t vb_c = ((g >> 1) << 3) * 2;            // V frag: n-col bytes

    const int row_lo = w * 16 + (lane >> 2);              // block-local rows
    const int n_tiles = 2 * (bq + 1);

    for (int jt = 0; jt < n_tiles; jt++) {
        const int j0 = jt << 6;

        // ---- stage K,V tile (64x64 each) ----
        float4 kv4[4], vv4[4];
        #pragma unroll
        for (int u = 0; u < 4; u++) {
            int idx = t + u * 256;
            int row = idx >> 4;
            int c4  = (idx & 15) << 2;
            kv4[u] = *(const float4*)(Kh + (size_t)(j0 + row) * DH + c4);
            vv4[u] = *(const float4*)(Vh + (size_t)(j0 + row) * DH + c4);
        }
        __syncthreads();   // previous tile's ldmatrix reads complete
        #pragma unroll
        for (int u = 0; u < 4; u++) {
            int idx = t + u * 256;
            int row = idx >> 4;
            int c4  = (idx & 15) << 2;
            uint2 hv, lv;
            split_bf16x3(kv4[u], hv, lv);
            *(uint2*)(sh + KHo + row * ARS + c4) = hv;
            *(uint2*)(sh + KLo + row * ARS + c4) = lv;
            split_bf16x3(vv4[u], hv, lv);
            *(uint2*)(sh + VHo + row * ARS + c4) = hv;
            *(uint2*)(sh + VLo + row * ARS + c4) = lv;
        }
        __syncthreads();

        // fully-masked tile for this warp -> skip compute (syncs already done)
        if (j0 > i0 + w * 16 + 15) continue;

        // ---- S = Q K^T (bf16x3, 3 passes) ----
        float sacc[8][4];
        #pragma unroll
        for (int nf = 0; nf < 8; nf++)
            #pragma unroll
            for (int e = 0; e < 4; e++) sacc[nf][e] = 0.0f;

        #pragma unroll
        for (int ks = 0; ks < 4; ks++) {
            uint32_t kb[4][4];
            #pragma unroll
            for (int kg = 0; kg < 4; kg++)
                LDSM_X4(kb[kg][0], kb[kg][1], kb[kg][2], kb[kg][3],
                        sb + KHo * 2 + (kg * 16 + kb_r) * (ARS * 2) + ks * 32 + kb_c);
            #pragma unroll
            for (int nf = 0; nf < 8; nf++) {
                const uint32_t* b = kb[nf >> 1] + ((nf & 1) << 1);
                MMA16816(sacc[nf], qhi[ks], b[0], b[1]);
            }
            #pragma unroll
            for (int nf = 0; nf < 8; nf++) {
                const uint32_t* b = kb[nf >> 1] + ((nf & 1) << 1);
                MMA16816(sacc[nf], qlo[ks], b[0], b[1]);
            }
            #pragma unroll
            for (int kg = 0; kg < 4; kg++)
                LDSM_X4(kb[kg][0], kb[kg][1], kb[kg][2], kb[kg][3],
                        sb + KLo * 2 + (kg * 16 + kb_r) * (ARS * 2) + ks * 32 + kb_c);
            #pragma unroll
            for (int nf = 0; nf < 8; nf++) {
                const uint32_t* b = kb[nf >> 1] + ((nf & 1) << 1);
                MMA16816(sacc[nf], qhi[ks], b[0], b[1]);
            }
        }

        // ---- softmax update ----
        const bool needmask = (j0 + 63 > i0 + w * 16);
        #pragma unroll
        for (int nf = 0; nf < 8; nf++) {
            #pragma unroll
            for (int e = 0; e < 4; e++) {
                float v = sacc[nf][e] * 0.125f;
                if (needmask) {
                    int col = j0 + nf * 8 + ((lane & 3) << 1) + (e & 1);
                    int row = i0 + row_lo + ((e >> 1) << 3);
                    if (col > row) v = -1e30f;
                }
                sacc[nf][e] = v;
            }
        }
        float mt0 = -1e30f, mt1 = -1e30f;
        #pragma unroll
        for (int nf = 0; nf < 8; nf++) {
            mt0 = fmaxf(mt0, fmaxf(sacc[nf][0], sacc[nf][1]));
            mt1 = fmaxf(mt1, fmaxf(sacc[nf][2], sacc[nf][3]));
        }
        mt0 = fmaxf(mt0, __shfl_xor_sync(0xffffffffu, mt0, 1));
        mt0 = fmaxf(mt0, __shfl_xor_sync(0xffffffffu, mt0, 2));
        mt1 = fmaxf(mt1, __shfl_xor_sync(0xffffffffu, mt1, 1));
        mt1 = fmaxf(mt1, __shfl_xor_sync(0xffffffffu, mt1, 2));

        float mn0 = fmaxf(m0, mt0), mn1 = fmaxf(m1, mt1);
        float a0 = __expf(m0 - mn0), a1 = __expf(m1 - mn1);
        m0 = mn0; m1 = mn1;

        float s0 = 0.0f, s1 = 0.0f;
        #pragma unroll
        for (int nf = 0; nf < 8; nf++) {
            sacc[nf][0] = __expf(sacc[nf][0] - m0);
            sacc[nf][1] = __expf(sacc[nf][1] - m0);
            sacc[nf][2] = __expf(sacc[nf][2] - m1);
            sacc[nf][3] = __expf(sacc[nf][3] - m1);
            s0 += sacc[nf][0] + sacc[nf][1];
            s1 += sacc[nf][2] + sacc[nf][3];
        }
        s0 += __shfl_xor_sync(0xffffffffu, s0, 1);
        s0 += __shfl_xor_sync(0xffffffffu, s0, 2);
        s1 += __shfl_xor_sync(0xffffffffu, s1, 1);
        s1 += __shfl_xor_sync(0xffffffffu, s1, 2);
        l0 = l0 * a0 + s0;
        l1 = l1 * a1 + s1;
        #pragma unroll
        for (int nf = 0; nf < 8; nf++) {
            oacc[nf][0] *= a0; oacc[nf][1] *= a0;
            oacc[nf][2] *= a1; oacc[nf][3] *= a1;
        }

        // ---- O += P V (bf16x3; P frags straight from registers) ----
        #pragma unroll
        for (int ks = 0; ks < 4; ks++) {
            uint32_t phi[4], plo[4];
            #pragma unroll
            for (int half = 0; half < 2; half++) {
                const float* p = sacc[2 * ks + half];
                __nv_bfloat162 h01 = __floats2bfloat162_rn(p[0], p[1]);
                __nv_bfloat162 h23 = __floats2bfloat162_rn(p[2], p[3]);
                __nv_bfloat162 l01 = __floats2bfloat162_rn(
                    p[0] - __bfloat162float(h01.x), p[1] - __bfloat162float(h01.y));
                __nv_bfloat162 l23 = __floats2bfloat162_rn(
                    p[2] - __bfloat162float(h23.x), p[3] - __bfloat162float(h23.y));
                phi[half * 2 + 0] = *reinterpret_cast<uint32_t*>(&h01);
                phi[half * 2 + 1] = *reinterpret_cast<uint32_t*>(&h23);
                plo[half * 2 + 0] = *reinterpret_cast<uint32_t*>(&l01);
                plo[half * 2 + 1] = *reinterpret_cast<uint32_t*>(&l23);
            }
            // wait: a-frag order must be {(r,k0),(r+8,k0),(r,k8),(r+8,k8)}
            // half0 gives (r,k0..1 block)=h01? h01 packs p[0],p[1] = (r, cols)
            // and h23 = (r+8). half1 = k+8 halves. Order already correct:
            // phi = { (r,klo), (r+8,klo), (r,khi), (r+8,khi) }  ✓
            uint32_t vb[4][4];
            #pragma unroll
            for (int kg = 0; kg < 4; kg++)
                LDSM_X4_T(vb[kg][0], vb[kg][1], vb[kg][2], vb[kg][3],
                          sb + VHo * 2 + (ks * 16 + vb_r) * (ARS * 2) + kg * 32 + vb_c);
            #pragma unroll
            for (int nf = 0; nf < 8; nf++) {
                const uint32_t* b = vb[nf >> 1] + ((nf & 1) << 1);
                MMA16816(oacc[nf], phi, b[0], b[1]);
            }
            #pragma unroll
            for (int nf = 0; nf < 8; nf++) {
                const uint32_t* b = vb[nf >> 1] + ((nf & 1) << 1);
                MMA16816(oacc[nf], plo, b[0], b[1]);
            }
            #pragma unroll
            for (int kg = 0; kg < 4; kg++)
                LDSM_X4_T(vb[kg][0], vb[kg][1], vb[kg][2], vb[kg][3],
                          sb + VLo * 2 + (ks * 16 + vb_r) * (ARS * 2) + kg * 32 + vb_c);
            #pragma unroll
            for (int nf = 0; nf < 8; nf++) {
                const uint32_t* b = vb[nf >> 1] + ((nf & 1) << 1);
                MMA16816(oacc[nf], phi, b[0], b[1]);
            }
        }
    }

    // ---- normalize + store ----
    const float inv0 = 1.0f / l0, inv1 = 1.0f / l1;
    const int r0 = i0 + row_lo;
    #pragma unroll
    for (int nf = 0; nf < 8; nf++) {
        int col = nf * 8 + ((lane & 3) << 1);
        *(float2*)(O + ((size_t)h * S + r0) * DH + col) =
            make_float2(oacc[nf][0] * inv0, oacc[nf][1] * inv0);
        *(float2*)(O + ((size_t)h * S + r0 + 8) * DH + col) =
            make_float2(oacc[nf][2] * inv1, oacc[nf][3] * inv1);
    }
}

// ---------------------------------------------------------------------------
extern "C" void kernel_launch(void* const* d_in, const int* in_sizes, int n_in,
                              void* d_out, int out_size)
{
    const float* Xq = (const float*)d_in[0];
    const float* Xk = (const float*)d_in[1];
    const float* Xv = (const float*)d_in[2];
    const float* Wq = (const float*)d_in[3];
    const float* bq = (const float*)d_in[4];
    const float* Wk = (const float*)d_in[5];
    const float* bk = (const float*)d_in[6];
    const float* Wv = (const float*)d_in[7];
    const float* bv = (const float*)d_in[8];
    const float* Wo = (const float*)d_in[9];
    const float* bo = (const float*)d_in[10];
    float* out = (float*)d_out;

    const int S = in_sizes[0] / DD;   // 4096

    float *q, *k, *v, *ctx;
    cudaGetSymbolAddress((void**)&q,   g_q);
    cudaGetSymbolAddress((void**)&k,   g_k);
    cudaGetSymbolAddress((void**)&v,   g_v);
    cudaGetSymbolAddress((void**)&ctx, g_ctx);

    cudaFuncSetAttribute(attn_mma,
                         cudaFuncAttributeMaxDynamicSharedMemorySize, ATTN_SMEM);

    dim3 gproj(DD / 128, S / 128);   // (8, 32)

    gemm_mma<0, 1><<<gproj, 256>>>(Xq, Wq, bq, q, DD, DD, S);
    gemm_mma<0, 1><<<gproj, 256>>>(Xk, Wk, bk, k, DD, DD, S);
    gemm_mma<0, 1><<<gproj, 256>>>(Xv, Wv, bv, v, DD, DD, S);

    attn_mma<<<dim3(S / 128, HH), 256, ATTN_SMEM>>>(q, k, v, ctx, S);

    gemm_mma<1, 0><<<gproj, 256>>>(ctx, Wo, bo, out, DD, DD, S);
}

// round 13
// speedup vs baseline: 3.2395x; 1.0715x over previous
#include <cuda_runtime.h>
#include <cuda_bf16.h>
#include <cstdint>

#define HH   16
#define DH   64
#define DD   1024
#define SMAX 4096

// Scratch (allocation-free rule: __device__ globals). Head-major [H][S][64].
__device__ float g_q[HH * SMAX * DH];
__device__ float g_k[HH * SMAX * DH];
__device__ float g_v[HH * SMAX * DH];
__device__ float g_ctx[HH * SMAX * DH];

// ===========================================================================
// Warp-level tensor core primitives (baseline PTX, works on compute_103)
// ===========================================================================
__device__ __forceinline__ uint32_t smem_u32(const void* p) {
    uint32_t a;
    asm("{ .reg .u64 t; cvta.to.shared.u64 t, %1; cvt.u32.u64 %0, t; }"
        : "=r"(a) : "l"(p));
    return a;
}

#define LDSM_X4(r0, r1, r2, r3, addr)                                        \
    asm volatile("ldmatrix.sync.aligned.m8n8.x4.shared.b16 {%0,%1,%2,%3}, [%4];" \
                 : "=r"(r0), "=r"(r1), "=r"(r2), "=r"(r3) : "r"(addr))

#define LDSM_X4_T(r0, r1, r2, r3, addr)                                      \
    asm volatile("ldmatrix.sync.aligned.m8n8.x4.trans.shared.b16 {%0,%1,%2,%3}, [%4];" \
                 : "=r"(r0), "=r"(r1), "=r"(r2), "=r"(r3) : "r"(addr))

#define MMA16816(d, a, b0, b1)                                               \
    asm volatile("mma.sync.aligned.m16n8k16.row.col.f32.bf16.bf16.f32 "     \
                 "{%0,%1,%2,%3}, {%4,%5,%6,%7}, {%8,%9}, {%0,%1,%2,%3};"    \
                 : "+f"((d)[0]), "+f"((d)[1]), "+f"((d)[2]), "+f"((d)[3])    \
                 : "r"((a)[0]), "r"((a)[1]), "r"((a)[2]), "r"((a)[3]),       \
                   "r"(b0), "r"(b1))

// Split float4 into bf16 hi + bf16 lo residual, packed as uint2 each.
__device__ __forceinline__ void split_bf16x3(float4 v, uint2& hv, uint2& lv) {
    __nv_bfloat162 h0 = __floats2bfloat162_rn(v.x, v.y);
    __nv_bfloat162 h1 = __floats2bfloat162_rn(v.z, v.w);
    float rx = v.x - __bfloat162float(h0.x);
    float ry = v.y - __bfloat162float(h0.y);
    float rz = v.z - __bfloat162float(h1.x);
    float rw = v.w - __bfloat162float(h1.y);
    __nv_bfloat162 l0 = __floats2bfloat162_rn(rx, ry);
    __nv_bfloat162 l1 = __floats2bfloat162_rn(rz, rw);
    hv = make_uint2(*reinterpret_cast<uint32_t*>(&h0),
                    *reinterpret_cast<uint32_t*>(&h1));
    lv = make_uint2(*reinterpret_cast<uint32_t*>(&l0),
                    *reinterpret_cast<uint32_t*>(&l1));
}

// ===========================================================================
// Tensor-core bf16x3 GEMM body (NT): C[M,N] = A[M,K] * B[N,K]^T + bias[N]
// ===========================================================================
#define RS    40
#define TOFF  (128 * RS)

template<int A_HM, int C_HM>
__device__ __forceinline__ void gemm_dev(
    const float* __restrict__ A, const float* __restrict__ B,
    const float* __restrict__ bias, float* __restrict__ C,
    int N, int Kd, int S)
{
    __shared__ __nv_bfloat16 sh[4 * TOFF];
    const uint32_t sb = smem_u32(sh);
    const uint32_t AH = sb, AL = sb + TOFF * 2,
                   BH = sb + 2 * TOFF * 2, BL = sb + 3 * TOFF * 2;

    const int t    = threadIdx.x;
    const int lane = t & 31, wid = t >> 5;
    const int wm   = wid >> 2;
    const int wn   = wid & 3;
    const int m0   = blockIdx.y << 7, n0 = blockIdx.x << 7;

    const int lrow = t >> 3;
    const int lc4  = (t & 7) << 2;

    const int a_r  = wm * 64 + (lane & 15);
    const int a_c  = (lane >> 4) << 3;
    const int b_g  = lane >> 3;
    const int b_r  = wn * 32 + ((b_g >> 1) << 3) + (lane & 7);
    const int b_c  = (b_g & 1) << 3;

    float acc[4][4][4];
    #pragma unroll
    for (int i = 0; i < 4; i++)
        #pragma unroll
        for (int j = 0; j < 4; j++)
            #pragma unroll
            for (int r = 0; r < 4; r++) acc[i][j][r] = 0.0f;

    const int nch = Kd >> 5;

    float4 av[4], bv[4];
    #pragma unroll
    for (int u = 0; u < 4; u++) {
        int row = lrow + (u << 5);
        if (A_HM)
            av[u] = *(const float4*)(A + (size_t)(m0 + row) * DH + lc4);
        else
            av[u] = *(const float4*)(A + (size_t)(m0 + row) * Kd + lc4);
        bv[u] = *(const float4*)(B + (size_t)(n0 + row) * Kd + lc4);
    }

    for (int i = 0; i < nch; i++) {
        __syncthreads();
        #pragma unroll
        for (int u = 0; u < 4; u++) {
            int row = lrow + (u << 5);
            uint32_t eo = row * RS + lc4;
            uint2 hv, lv;
            split_bf16x3(av[u], hv, lv);
            *(uint2*)(sh + eo)            = hv;
            *(uint2*)(sh + TOFF + eo)     = lv;
            split_bf16x3(bv[u], hv, lv);
            *(uint2*)(sh + 2 * TOFF + eo) = hv;
            *(uint2*)(sh + 3 * TOFF + eo) = lv;
        }
        __syncthreads();

        if (i + 1 < nch) {
            const int k0 = (i + 1) << 5;
            #pragma unroll
            for (int u = 0; u < 4; u++) {
                int row = lrow + (u << 5);
                if (A_HM)
                    av[u] = *(const float4*)(A + ((size_t)(k0 >> 6) * S + m0 + row) * DH
                                               + (k0 & 63) + lc4);
                else
                    av[u] = *(const float4*)(A + (size_t)(m0 + row) * Kd + k0 + lc4);
                bv[u] = *(const float4*)(B + (size_t)(n0 + row) * Kd + k0 + lc4);
            }
        }

        #pragma unroll
        for (int ks = 0; ks < 2; ks++) {
            const uint32_t acol = (a_c + (ks << 4)) << 1;
            const uint32_t bcol = (b_c + (ks << 4)) << 1;

            uint32_t aH[4][4], aL[4][4], bh[2][4], bl[2][4];
            #pragma unroll
            for (int mf = 0; mf < 4; mf++) {
                uint32_t ra = (uint32_t)(a_r + mf * 16) * (RS * 2);
                LDSM_X4(aH[mf][0], aH[mf][1], aH[mf][2], aH[mf][3], AH + ra + acol);
            }
            #pragma unroll
            for (int ng = 0; ng < 2; ng++) {
                uint32_t rb = (uint32_t)(b_r + ng * 16) * (RS * 2);
                LDSM_X4(bh[ng][0], bh[ng][1], bh[ng][2], bh[ng][3], BH + rb + bcol);
            }
            #pragma unroll
            for (int mf = 0; mf < 4; mf++)
                #pragma unroll
                for (int nf = 0; nf < 4; nf++) {
                    const uint32_t* b = bh[nf >> 1] + ((nf & 1) << 1);
                    MMA16816(acc[mf][nf], aH[mf], b[0], b[1]);
                }
            #pragma unroll
            for (int ng = 0; ng < 2; ng++) {
                uint32_t rb = (uint32_t)(b_r + ng * 16) * (RS * 2);
                LDSM_X4(bl[ng][0], bl[ng][1], bl[ng][2], bl[ng][3], BL + rb + bcol);
            }
            #pragma unroll
            for (int mf = 0; mf < 4; mf++)
                #pragma unroll
                for (int nf = 0; nf < 4; nf++) {
                    const uint32_t* b = bl[nf >> 1] + ((nf & 1) << 1);
                    MMA16816(acc[mf][nf], aH[mf], b[0], b[1]);
                }
            #pragma unroll
            for (int mf = 0; mf < 4; mf++) {
                uint32_t ra = (uint32_t)(a_r + mf * 16) * (RS * 2);
                LDSM_X4(aL[mf][0], aL[mf][1], aL[mf][2], aL[mf][3], AL + ra + acol);
            }
            #pragma unroll
            for (int mf = 0; mf < 4; mf++)
                #pragma unroll
                for (int nf = 0; nf < 4; nf++) {
                    const uint32_t* b = bh[nf >> 1] + ((nf & 1) << 1);
                    MMA16816(acc[mf][nf], aL[mf], b[0], b[1]);
                }
        }
    }

    const int er = lane >> 2;
    const int ec = (lane & 3) << 1;
    #pragma unroll
    for (int mf = 0; mf < 4; mf++) {
        #pragma unroll
        for (int nf = 0; nf < 4; nf++) {
            int col  = n0 + wn * 32 + nf * 8 + ec;
            float bx = bias[col], by = bias[col + 1];
            int r0 = m0 + wm * 64 + mf * 16 + er;
            int r1 = r0 + 8;
            float2 o0 = make_float2(acc[mf][nf][0] + bx, acc[mf][nf][1] + by);
            float2 o1 = make_float2(acc[mf][nf][2] + bx, acc[mf][nf][3] + by);
            if (C_HM) {
                size_t base = (size_t)(col >> 6) * S;
                *(float2*)(C + (base + r0) * DH + (col & 63)) = o0;
                *(float2*)(C + (base + r1) * DH + (col & 63)) = o1;
            } else {
                *(float2*)(C + (size_t)r0 * N + col) = o0;
                *(float2*)(C + (size_t)r1 * N + col) = o1;
            }
        }
    }
}

// Fused Q/K/V projections: blockIdx.z selects the input/weight/output set.
__global__ __launch_bounds__(256) void gemm_qkv(
    const float* __restrict__ Xq, const float* __restrict__ Xk,
    const float* __restrict__ Xv,
    const float* __restrict__ Wq, const float* __restrict__ bq_,
    const float* __restrict__ Wk, const float* __restrict__ bk_,
    const float* __restrict__ Wv, const float* __restrict__ bv_,
    float* __restrict__ q, float* __restrict__ k, float* __restrict__ v,
    int N, int Kd, int S)
{
    const float *A, *B, *bias;
    float* C;
    if (blockIdx.z == 0)      { A = Xq; B = Wq; bias = bq_; C = q; }
    else if (blockIdx.z == 1) { A = Xk; B = Wk; bias = bk_; C = k; }
    else                      { A = Xv; B = Wv; bias = bv_; C = v; }
    gemm_dev<0, 1>(A, B, bias, C, N, Kd, S);
}

__global__ __launch_bounds__(256) void gemm_out(
    const float* __restrict__ A, const float* __restrict__ B,
    const float* __restrict__ bias, float* __restrict__ C,
    int N, int Kd, int S)
{
    gemm_dev<1, 0>(A, B, bias, C, N, Kd, S);
}

// ===========================================================================
// Tensor-core causal flash attention (bf16x3), double-buffered K/V staging.
// One CTA = (head, 128 q rows), 8 warps, warp w owns rows [w*16, w*16+16).
// kv tiles of 64. One __syncthreads per tile; LDG prefetched 2 tiles ahead.
// Q staged in buffer 0, freed to K/V use after fragments move to registers.
// ===========================================================================
#define ARS   72
#define BUFE  18432            // bf16 elems per K/V buffer
#define KHo   0
#define KLo   4608
#define VHo   9216
#define VLo   13824
#define QLoO  9216             // Q lo offset (Q hi at 0), within buffer 0
#define ATTN_SMEM (2 * BUFE * 2)   // 73728 bytes

__global__ __launch_bounds__(256) void attn_mma(
    const float* __restrict__ Q, const float* __restrict__ K,
    const float* __restrict__ V, float* __restrict__ O, int S)
{
    extern __shared__ __nv_bfloat16 sh[];
    const uint32_t sb = smem_u32(sh);

    const int h  = blockIdx.y;
    const int bq = gridDim.x - 1 - blockIdx.x;   // longest CTAs first
    const int i0 = bq << 7;
    const float* Qh = Q + (size_t)h * S * DH;
    const float* Kh = K + (size_t)h * S * DH;
    const float* Vh = V + (size_t)h * S * DH;

    const int t = threadIdx.x, lane = t & 31, w = t >> 5;

    // ---- stage Q (128x64) as hi/lo bf16 into buffer 0 ----
    #pragma unroll
    for (int u = 0; u < 8; u++) {
        int idx = t + u * 256;
        int row = idx >> 4;
        int c4  = (idx & 15) << 2;
        float4 qv = *(const float4*)(Qh + (size_t)(i0 + row) * DH + c4);
        uint2 hv, lv;
        split_bf16x3(qv, hv, lv);
        *(uint2*)(sh + row * ARS + c4)        = hv;
        *(uint2*)(sh + QLoO + row * ARS + c4) = lv;
    }
    __syncthreads();

    // ---- Q fragments (registers for the whole kernel) ----
    uint32_t qhi[4][4], qlo[4][4];
    {
        const uint32_t ar = (uint32_t)(w * 16 + (lane & 15)) * (ARS * 2);
        const uint32_t ac = ((lane >> 4) << 3) * 2;
        #pragma unroll
        for (int ks = 0; ks < 4; ks++) {
            LDSM_X4(qhi[ks][0], qhi[ks][1], qhi[ks][2], qhi[ks][3],
                    sb + ar + ac + ks * 32);
            LDSM_X4(qlo[ks][0], qlo[ks][1], qlo[ks][2], qlo[ks][3],
                    sb + QLoO * 2 + ar + ac + ks * 32);
        }
    }

    float oacc[8][4];
    #pragma unroll
    for (int nf = 0; nf < 8; nf++)
        #pragma unroll
        for (int e = 0; e < 4; e++) oacc[nf][e] = 0.0f;
    float m0 = -1e30f, m1 = -1e30f, l0 = 0.0f, l1 = 0.0f;

    const int g    = lane >> 3;
    const uint32_t kb_r = ((g >> 1) << 3) + (lane & 7);
    const uint32_t kb_c = ((g & 1) << 3) * 2;
    const uint32_t vb_r = ((g & 1) << 3) + (lane & 7);
    const uint32_t vb_c = ((g >> 1) << 3) * 2;

    const int row_lo  = w * 16 + (lane >> 2);
    const int n_tiles = 2 * (bq + 1);

    const int lrow = t >> 4;            // staging row
    const int lc4  = (t & 15) << 2;     // staging col

    // ---- prologue: LDG tile0; sync (Q frags consumed); store; LDG tile1 ----
    float4 kv4[4], vv4[4];
    #pragma unroll
    for (int u = 0; u < 4; u++) {
        int row = lrow + (u << 4);
        kv4[u] = *(const float4*)(Kh + (size_t)row * DH + lc4);
        vv4[u] = *(const float4*)(Vh + (size_t)row * DH + lc4);
    }
    __syncthreads();
    #pragma unroll
    for (int u = 0; u < 4; u++) {
        int row = lrow + (u << 4);
        uint2 hv, lv;
        split_bf16x3(kv4[u], hv, lv);
        *(uint2*)(sh + KHo + row * ARS + lc4) = hv;
        *(uint2*)(sh + KLo + row * ARS + lc4) = lv;
        split_bf16x3(vv4[u], hv, lv);
        *(uint2*)(sh + VHo + row * ARS + lc4) = hv;
        *(uint2*)(sh + VLo + row * ARS + lc4) = lv;
    }
    if (n_tiles > 1) {
        #pragma unroll
        for (int u = 0; u < 4; u++) {
            int row = 64 + lrow + (u << 4);
            kv4[u] = *(const float4*)(Kh + (size_t)row * DH + lc4);
            vv4[u] = *(const float4*)(Vh + (size_t)row * DH + lc4);
        }
    }
    __syncthreads();

    for (int jt = 0; jt < n_tiles; jt++) {
        const int j0   = jt << 6;
        const uint32_t bo  = (uint32_t)(jt & 1) * (BUFE * 2);   // byte offset
        __nv_bfloat16* bpe = sh + (jt & 1) * BUFE;               // elem ptr (unused in mma)

        if (j0 <= i0 + w * 16 + 15) {
            // ---- S = Q K^T (bf16x3, 3 passes) ----
            float sacc[8][4];
            #pragma unroll
            for (int nf = 0; nf < 8; nf++)
                #pragma unroll
                for (int e = 0; e < 4; e++) sacc[nf][e] = 0.0f;

            #pragma unroll
            for (int ks = 0; ks < 4; ks++) {
                uint32_t kb[4][4];
                #pragma unroll
                for (int kg = 0; kg < 4; kg++)
                    LDSM_X4(kb[kg][0], kb[kg][1], kb[kg][2], kb[kg][3],
                            sb + bo + KHo * 2 + (kg * 16 + kb_r) * (ARS * 2) + ks * 32 + kb_c);
                #pragma unroll
                for (int nf = 0; nf < 8; nf++) {
                    const uint32_t* b = kb[nf >> 1] + ((nf & 1) << 1);
                    MMA16816(sacc[nf], qhi[ks], b[0], b[1]);
                }
                #pragma unroll
                for (int nf = 0; nf < 8; nf++) {
                    const uint32_t* b = kb[nf >> 1] + ((nf & 1) << 1);
                    MMA16816(sacc[nf], qlo[ks], b[0], b[1]);
                }
                #pragma unroll
                for (int kg = 0; kg < 4; kg++)
                    LDSM_X4(kb[kg][0], kb[kg][1], kb[kg][2], kb[kg][3],
                            sb + bo + KLo * 2 + (kg * 16 + kb_r) * (ARS * 2) + ks * 32 + kb_c);
                #pragma unroll
                for (int nf = 0; nf < 8; nf++) {
                    const uint32_t* b = kb[nf >> 1] + ((nf & 1) << 1);
                    MMA16816(sacc[nf], qhi[ks], b[0], b[1]);
                }
            }

            // ---- softmax update ----
            const bool needmask = (j0 + 63 > i0 + w * 16);
            #pragma unroll
            for (int nf = 0; nf < 8; nf++) {
                #pragma unroll
                for (int e = 0; e < 4; e++) {
                    float v = sacc[nf][e] * 0.125f;
                    if (needmask) {
                        int col = j0 + nf * 8 + ((lane & 3) << 1) + (e & 1);
                        int row = i0 + row_lo + ((e >> 1) << 3);
                        if (col > row) v = -1e30f;
                    }
                    sacc[nf][e] = v;
                }
            }
            float mt0 = -1e30f, mt1 = -1e30f;
            #pragma unroll
            for (int nf = 0; nf < 8; nf++) {
                mt0 = fmaxf(mt0, fmaxf(sacc[nf][0], sacc[nf][1]));
                mt1 = fmaxf(mt1, fmaxf(sacc[nf][2], sacc[nf][3]));
            }
            mt0 = fmaxf(mt0, __shfl_xor_sync(0xffffffffu, mt0, 1));
            mt0 = fmaxf(mt0, __shfl_xor_sync(0xffffffffu, mt0, 2));
            mt1 = fmaxf(mt1, __shfl_xor_sync(0xffffffffu, mt1, 1));
            mt1 = fmaxf(mt1, __shfl_xor_sync(0xffffffffu, mt1, 2));

            float mn0 = fmaxf(m0, mt0), mn1 = fmaxf(m1, mt1);
            float a0 = __expf(m0 - mn0), a1 = __expf(m1 - mn1);
            m0 = mn0; m1 = mn1;

            float s0 = 0.0f, s1 = 0.0f;
            #pragma unroll
            for (int nf = 0; nf < 8; nf++) {
                sacc[nf][0] = __expf(sacc[nf][0] - m0);
                sacc[nf][1] = __expf(sacc[nf][1] - m0);
                sacc[nf][2] = __expf(sacc[nf][2] - m1);
                sacc[nf][3] = __expf(sacc[nf][3] - m1);
                s0 += sacc[nf][0] + sacc[nf][1];
                s1 += sacc[nf][2] + sacc[nf][3];
            }
            s0 += __shfl_xor_sync(0xffffffffu, s0, 1);
            s0 += __shfl_xor_sync(0xffffffffu, s0, 2);
            s1 += __shfl_xor_sync(0xffffffffu, s1, 1);
            s1 += __shfl_xor_sync(0xffffffffu, s1, 2);
            l0 = l0 * a0 + s0;
            l1 = l1 * a1 + s1;
            #pragma unroll
            for (int nf = 0; nf < 8; nf++) {
                oacc[nf][0] *= a0; oacc[nf][1] *= a0;
                oacc[nf][2] *= a1; oacc[nf][3] *= a1;
            }

            // ---- O += P V (bf16x3; P frags straight from registers) ----
            #pragma unroll
            for (int ks = 0; ks < 4; ks++) {
                uint32_t phi[4], plo[4];
                #pragma unroll
                for (int half = 0; half < 2; half++) {
                    const float* p = sacc[2 * ks + half];
                    __nv_bfloat162 h01 = __floats2bfloat162_rn(p[0], p[1]);
                    __nv_bfloat162 h23 = __floats2bfloat162_rn(p[2], p[3]);
                    __nv_bfloat162 l01 = __floats2bfloat162_rn(
                        p[0] - __bfloat162float(h01.x), p[1] - __bfloat162float(h01.y));
                    __nv_bfloat162 l23 = __floats2bfloat162_rn(
                        p[2] - __bfloat162float(h23.x), p[3] - __bfloat162float(h23.y));
                    phi[half * 2 + 0] = *reinterpret_cast<uint32_t*>(&h01);
                    phi[half * 2 + 1] = *reinterpret_cast<uint32_t*>(&h23);
                    plo[half * 2 + 0] = *reinterpret_cast<uint32_t*>(&l01);
                    plo[half * 2 + 1] = *reinterpret_cast<uint32_t*>(&l23);
                }
                uint32_t vb[4][4];
                #pragma unroll
                for (int kg = 0; kg < 4; kg++)
                    LDSM_X4_T(vb[kg][0], vb[kg][1], vb[kg][2], vb[kg][3],
                              sb + bo + VHo * 2 + (ks * 16 + vb_r) * (ARS * 2) + kg * 32 + vb_c);
                #pragma unroll
                for (int nf = 0; nf < 8; nf++) {
                    const uint32_t* b = vb[nf >> 1] + ((nf & 1) << 1);
                    MMA16816(oacc[nf], phi, b[0], b[1]);
                }
                #pragma unroll
                for (int nf = 0; nf < 8; nf++) {
                    const uint32_t* b = vb[nf >> 1] + ((nf & 1) << 1);
                    MMA16816(oacc[nf], plo, b[0], b[1]);
                }
                #pragma unroll
                for (int kg = 0; kg < 4; kg++)
                    LDSM_X4_T(vb[kg][0], vb[kg][1], vb[kg][2], vb[kg][3],
                              sb + bo + VLo * 2 + (ks * 16 + vb_r) * (ARS * 2) + kg * 32 + vb_c);
                #pragma unroll
                for (int nf = 0; nf < 8; nf++) {
                    const uint32_t* b = vb[nf >> 1] + ((nf & 1) << 1);
                    MMA16816(oacc[nf], phi, b[0], b[1]);
                }
            }
        }
        (void)bpe;

        // ---- stage tile jt+1 (regs -> buf[(jt+1)&1]); LDG tile jt+2 ----
        if (jt + 1 < n_tiles) {
            __nv_bfloat16* dst = sh + ((jt + 1) & 1) * BUFE;
            #pragma unroll
            for (int u = 0; u < 4; u++) {
                int row = lrow + (u << 4);
                uint2 hv, lv;
                split_bf16x3(kv4[u], hv, lv);
                *(uint2*)(dst + KHo + row * ARS + lc4) = hv;
                *(uint2*)(dst + KLo + row * ARS + lc4) = lv;
                split_bf16x3(vv4[u], hv, lv);
                *(uint2*)(dst + VHo + row * ARS + lc4) = hv;
                *(uint2*)(dst + VLo + row * ARS + lc4) = lv;
            }
            if (jt + 2 < n_tiles) {
                const int jn = (jt + 2) << 6;
                #pragma unroll
                for (int u = 0; u < 4; u++) {
                    int row = jn + lrow + (u << 4);
                    kv4[u] = *(const float4*)(Kh + (size_t)row * DH + lc4);
                    vv4[u] = *(const float4*)(Vh + (size_t)row * DH + lc4);
                }
            }
        }
        __syncthreads();
    }

    // ---- normalize + store ----
    const float inv0 = 1.0f / l0, inv1 = 1.0f / l1;
    const int r0 = i0 + row_lo;
    #pragma unroll
    for (int nf = 0; nf < 8; nf++) {
        int col = nf * 8 + ((lane & 3) << 1);
        *(float2*)(O + ((size_t)h * S + r0) * DH + col) =
            make_float2(oacc[nf][0] * inv0, oacc[nf][1] * inv0);
        *(float2*)(O + ((size_t)h * S + r0 + 8) * DH + col) =
            make_float2(oacc[nf][2] * inv1, oacc[nf][3] * inv1);
    }
}

// ---------------------------------------------------------------------------
extern "C" void kernel_launch(void* const* d_in, const int* in_sizes, int n_in,
                              void* d_out, int out_size)
{
    const float* Xq = (const float*)d_in[0];
    const float* Xk = (const float*)d_in[1];
    const float* Xv = (const float*)d_in[2];
    const float* Wq = (const float*)d_in[3];
    const float* bq = (const float*)d_in[4];
    const float* Wk = (const float*)d_in[5];
    const float* bk = (const float*)d_in[6];
    const float* Wv = (const float*)d_in[7];
    const float* bv = (const float*)d_in[8];
    const float* Wo = (const float*)d_in[9];
    const float* bo = (const float*)d_in[10];
    float* out = (float*)d_out;

    const int S = in_sizes[0] / DD;   // 4096

    float *q, *k, *v, *ctx;
    cudaGetSymbolAddress((void**)&q,   g_q);
    cudaGetSymbolAddress((void**)&k,   g_k);
    cudaGetSymbolAddress((void**)&v,   g_v);
    cudaGetSymbolAddress((void**)&ctx, g_ctx);

    cudaFuncSetAttribute(attn_mma,
                         cudaFuncAttributeMaxDynamicSharedMemorySize, ATTN_SMEM);

    gemm_qkv<<<dim3(DD / 128, S / 128, 3), 256>>>(
        Xq, Xk, Xv, Wq, bq, Wk, bk, Wv, bv, q, k, v, DD, DD, S);

    attn_mma<<<dim3(S / 128, HH), 256, ATTN_SMEM>>>(q, k, v, ctx, S);

    gemm_out<<<dim3(DD / 128, S / 128), 256>>>(ctx, Wo, bo, out, DD, DD, S);
}